// round 7
// baseline (speedup 1.0000x reference)
#include <cuda_runtime.h>
#include <cuda_bf16.h>
#include <math.h>
#include <stdint.h>

#define NN   50000
#define EE   800000
#define ET   (EE + NN)    // edges + self loops = 850000
#define INC  128
#define HC   256          // HEADS*HID
#define OUTC 40
#define NEG  0.2f

// ---------------- device scratch (no allocations allowed) ----------------
__device__ __nv_bfloat16  g_xh[(size_t)NN * INC];    // bf16 copy of x
__device__ __nv_bfloat16  g_bufHh[(size_t)NN * HC];  // bf16 h (GEMM out, layers 1-2)
__device__ __nv_bfloat16  g_bufAh[(size_t)NN * HC];  // bf16 aggregated (next GEMM in)
__device__ float          g_bufH3[(size_t)NN * OUTC];// fp32 h (layer 3)
__device__ float g_als[(size_t)NN * 4];
__device__ float g_ald[(size_t)NN * 4];
__device__ int   g_off[NN + 1];
__device__ int   g_cur[NN];
__device__ int   g_deg[NN];
__device__ int   g_csr[ET];
__device__ int   g_bsum[64];
__device__ int   g_i64flag;

__device__ __forceinline__ int edge_at(const void* ei, int f, long long pos) {
    return f ? (int)(((const long long*)ei)[pos]) : ((const int*)ei)[pos];
}

// ---------------- edge dtype detection ----------------
__global__ void k_detect(const int* ei32) {
    __shared__ int sAny[8];
    int bad = 0;
    for (int j = threadIdx.x; j < 4096; j += blockDim.x)
        if (ei32[2 * j + 1] != 0) bad = 1;
    unsigned any = __ballot_sync(0xffffffffu, bad);
    if ((threadIdx.x & 31) == 0) sAny[threadIdx.x >> 5] = (any != 0);
    __syncthreads();
    if (threadIdx.x == 0) {
        int t = 0;
        for (int w = 0; w < (int)(blockDim.x >> 5); w++) t |= sAny[w];
        g_i64flag = t ? 0 : 1;
    }
}

// ---------------- fused: dst histogram + x->bf16 conversion ----------------
__global__ void k_histcvt(const void* ei, const float* __restrict__ x,
                          __nv_bfloat16* __restrict__ xh) {
    int i = blockIdx.x * blockDim.x + threadIdx.x;
    if (i < NN * INC / 8) {
        const float4* p = (const float4*)(x + (size_t)i * 8);
        float4 a = p[0], b = p[1];
        uint4 u;
        *(__nv_bfloat162*)&u.x = __float22bfloat162_rn(make_float2(a.x, a.y));
        *(__nv_bfloat162*)&u.y = __float22bfloat162_rn(make_float2(a.z, a.w));
        *(__nv_bfloat162*)&u.z = __float22bfloat162_rn(make_float2(b.x, b.y));
        *(__nv_bfloat162*)&u.w = __float22bfloat162_rn(make_float2(b.z, b.w));
        *(uint4*)(xh + (size_t)i * 8) = u;
    }
    if (i < ET) {
        int f = g_i64flag;
        int d = (i < EE) ? edge_at(ei, f, (long long)EE + i) : (i - EE);
        atomicAdd(&g_deg[d], 1);
    }
}

#define SB 1024
__global__ void k_scan1() {
    __shared__ int sh[SB];
    int g = blockIdx.x * SB + threadIdx.x;
    int v = (g < NN) ? g_deg[g] : 0;
    sh[threadIdx.x] = v;
    __syncthreads();
    for (int o = 1; o < SB; o <<= 1) {
        int t = (threadIdx.x >= o) ? sh[threadIdx.x - o] : 0;
        __syncthreads();
        sh[threadIdx.x] += t;
        __syncthreads();
    }
    if (g < NN) g_off[g] = sh[threadIdx.x] - v;   // exclusive
    if (threadIdx.x == SB - 1) g_bsum[blockIdx.x] = sh[SB - 1];
}
// scan3 computes the block-sum prefix itself
__global__ void k_scan3(int nb) {
    __shared__ int sC[2];
    int t = threadIdx.x;
    if (t < 64) {
        int v = (t < nb && t < (int)blockIdx.x) ? g_bsum[t] : 0;
#pragma unroll
        for (int o = 16; o >= 1; o >>= 1) v += __shfl_xor_sync(0xffffffffu, v, o);
        if ((t & 31) == 0) sC[t >> 5] = v;
    }
    __syncthreads();
    int carry = sC[0] + sC[1];
    int g = blockIdx.x * SB + t;
    if (g < NN) g_off[g] += carry;
    if (g == 0) g_off[NN] = ET;
}

__global__ void k_scatter(const void* ei) {
    int e = blockIdx.x * blockDim.x + threadIdx.x;
    if (e >= ET) return;
    int f = g_i64flag;
    int s, d;
    if (e < EE) { s = edge_at(ei, f, e); d = edge_at(ei, f, (long long)EE + e); }
    else        { s = d = e - EE; }
    int p = g_off[d] + atomicAdd(&g_cur[d], 1);
    g_csr[p] = s;
}

// ---------------- bf16 MMA helpers ----------------
__device__ __forceinline__ void ldsm4(uint32_t* r, uint32_t addr) {
    asm volatile("ldmatrix.sync.aligned.m8n8.x4.shared.b16 {%0,%1,%2,%3}, [%4];"
                 : "=r"(r[0]), "=r"(r[1]), "=r"(r[2]), "=r"(r[3]) : "r"(addr));
}

__device__ __forceinline__ void mma_bf16(float4& d, const uint32_t* a, const uint32_t* b) {
    asm volatile(
        "mma.sync.aligned.m16n8k16.row.col.f32.bf16.bf16.f32 "
        "{%0,%1,%2,%3}, {%4,%5,%6,%7}, {%8,%9}, {%0,%1,%2,%3};\n"
        : "+f"(d.x), "+f"(d.y), "+f"(d.z), "+f"(d.w)
        : "r"(a[0]), "r"(a[1]), "r"(a[2]), "r"(a[3]), "r"(b[0]), "r"(b[1]));
}

__device__ __forceinline__ void store_c(__nv_bfloat16* C, size_t r, int stride, int col,
                                        float x, float y, int ncq) {
    *(__nv_bfloat162*)(C + r * stride + col) = __float22bfloat162_rn(make_float2(x, y));
}
__device__ __forceinline__ void store_c(float* C, size_t r, int stride, int col,
                                        float x, float y, int ncq) {
    if (col < ncq) *(float2*)(C + r * stride + col) = make_float2(x, y);
}

#define LDA 40  // padded smem row stride in bf16 elems

// ============ bf16 GEMM + fused attention projections =====================
template<int NCQ, int HSTR, typename CT>
__global__ __launch_bounds__(256) void k_gemmb(const __nv_bfloat16* __restrict__ A,
                                               const float* __restrict__ W,
                                               CT* __restrict__ C,
                                               const float* __restrict__ asv,
                                               const float* __restrict__ adv,
                                               float* __restrict__ als,
                                               float* __restrict__ ald,
                                               int M, int K) {
    __shared__ __nv_bfloat16 As[128 * LDA];
    __shared__ __nv_bfloat16 Bs[64 * LDA];
    __shared__ float sAls[128][2];
    __shared__ float sAld[128][2];
    int tid = threadIdx.x;
    int lane = tid & 31, warp = tid >> 5;
    int wm = warp & 3, wn = warp >> 2;
    int bm = blockIdx.y * 128, bn = blockIdx.x * 64;
    int head = blockIdx.x;

    float4 acc[2][4];
#pragma unroll
    for (int mt = 0; mt < 2; mt++)
#pragma unroll
        for (int nt = 0; nt < 4; nt++) acc[mt][nt] = make_float4(0.f, 0.f, 0.f, 0.f);

    uint4  ra[2];
    float4 rb[2];

#pragma unroll
    for (int i = 0; i < 2; i++) {
        int idx = i * 256 + tid;
        int row = idx >> 2, c8 = idx & 3;
        int gr = bm + row;
        ra[i] = (gr < M) ? *(const uint4*)(A + (size_t)gr * K + c8 * 8)
                         : make_uint4(0u, 0u, 0u, 0u);
    }
#pragma unroll
    for (int i = 0; i < 2; i++) {
        int idx = i * 256 + tid;
        int kr = idx >> 4, nc4 = idx & 15;
        int gc = bn + nc4 * 4;
        const float* wp = W + (size_t)kr * NCQ + gc;
        float4 v = make_float4(0.f, 0.f, 0.f, 0.f);
        if (NCQ >= 64 || gc + 3 < NCQ) {
            if (NCQ >= 64 || gc < NCQ) v = *(const float4*)wp;
        } else {
            if (gc + 0 < NCQ) v.x = wp[0];
            if (gc + 1 < NCQ) v.y = wp[1];
            if (gc + 2 < NCQ) v.z = wp[2];
            if (gc + 3 < NCQ) v.w = wp[3];
        }
        rb[i] = v;
    }

    uint32_t smA = (uint32_t)__cvta_generic_to_shared(As);
    uint32_t smB = (uint32_t)__cvta_generic_to_shared(Bs);

    for (int k0 = 0; k0 < K; k0 += 32) {
#pragma unroll
        for (int i = 0; i < 2; i++) {
            int idx = i * 256 + tid;
            int row = idx >> 2, c8 = idx & 3;
            *(uint4*)(As + row * LDA + c8 * 8) = ra[i];
        }
#pragma unroll
        for (int i = 0; i < 2; i++) {
            int idx = i * 256 + tid;
            int kr = idx >> 4, nc4 = idx & 15;
            Bs[(nc4 * 4 + 0) * LDA + kr] = __float2bfloat16(rb[i].x);
            Bs[(nc4 * 4 + 1) * LDA + kr] = __float2bfloat16(rb[i].y);
            Bs[(nc4 * 4 + 2) * LDA + kr] = __float2bfloat16(rb[i].z);
            Bs[(nc4 * 4 + 3) * LDA + kr] = __float2bfloat16(rb[i].w);
        }
        __syncthreads();

        int kn = k0 + 32;
        if (kn < K) {
#pragma unroll
            for (int i = 0; i < 2; i++) {
                int idx = i * 256 + tid;
                int row = idx >> 2, c8 = idx & 3;
                int gr = bm + row;
                ra[i] = (gr < M) ? *(const uint4*)(A + (size_t)gr * K + kn + c8 * 8)
                                 : make_uint4(0u, 0u, 0u, 0u);
            }
#pragma unroll
            for (int i = 0; i < 2; i++) {
                int idx = i * 256 + tid;
                int kr = idx >> 4, nc4 = idx & 15;
                int gc = bn + nc4 * 4;
                const float* wp = W + (size_t)(kn + kr) * NCQ + gc;
                float4 v = make_float4(0.f, 0.f, 0.f, 0.f);
                if (NCQ >= 64 || gc + 3 < NCQ) {
                    if (NCQ >= 64 || gc < NCQ) v = *(const float4*)wp;
                } else {
                    if (gc + 0 < NCQ) v.x = wp[0];
                    if (gc + 1 < NCQ) v.y = wp[1];
                    if (gc + 2 < NCQ) v.z = wp[2];
                    if (gc + 3 < NCQ) v.w = wp[3];
                }
                rb[i] = v;
            }
        }

#pragma unroll
        for (int ks = 0; ks < 2; ks++) {
            int kk = ks * 16;
            uint32_t afr[2][4], bfr[4][2];
#pragma unroll
            for (int mt = 0; mt < 2; mt++) {
                int mrow = wm * 32 + mt * 16 + (lane & 15);
                int kc = kk + ((lane >> 4) << 3);
                ldsm4(afr[mt], smA + (uint32_t)(mrow * LDA + kc) * 2u);
            }
#pragma unroll
            for (int nh = 0; nh < 2; nh++) {
                int nrow = wn * 32 + nh * 16 + ((lane >> 4) << 3) + (lane & 7);
                int kc = kk + (((lane >> 3) & 1) << 3);
                uint32_t tmp[4];
                ldsm4(tmp, smB + (uint32_t)(nrow * LDA + kc) * 2u);
                bfr[nh * 2 + 0][0] = tmp[0]; bfr[nh * 2 + 0][1] = tmp[1];
                bfr[nh * 2 + 1][0] = tmp[2]; bfr[nh * 2 + 1][1] = tmp[3];
            }
#pragma unroll
            for (int mt = 0; mt < 2; mt++)
#pragma unroll
                for (int nt = 0; nt < 4; nt++)
                    mma_bf16(acc[mt][nt], afr[mt], bfr[nt]);
        }
        __syncthreads();
    }

    int gq = lane >> 2, tq = lane & 3;
    const float* asvh = asv + head * 64;
    const float* advh = adv + head * 64;
#pragma unroll
    for (int mt = 0; mt < 2; mt++) {
        float va0 = 0.f, va1 = 0.f, vd0 = 0.f, vd1 = 0.f;
        int r0 = bm + wm * 32 + mt * 16 + gq;
        int r1 = r0 + 8;
#pragma unroll
        for (int nt = 0; nt < 4; nt++) {
            int cl = wn * 32 + nt * 8 + tq * 2;
            float4 d = acc[mt][nt];
            if (r0 < M) store_c(C, (size_t)r0, NCQ, bn + cl, d.x, d.y, NCQ);
            if (r1 < M) store_c(C, (size_t)r1, NCQ, bn + cl, d.z, d.w, NCQ);
            float a0 = (NCQ >= 64 || cl + 0 < NCQ) ? asvh[cl] : 0.f;
            float a1 = (NCQ >= 64 || cl + 1 < NCQ) ? asvh[cl + 1] : 0.f;
            float e0 = (NCQ >= 64 || cl + 0 < NCQ) ? advh[cl] : 0.f;
            float e1 = (NCQ >= 64 || cl + 1 < NCQ) ? advh[cl + 1] : 0.f;
            va0 += d.x * a0 + d.y * a1;
            va1 += d.z * a0 + d.w * a1;
            vd0 += d.x * e0 + d.y * e1;
            vd1 += d.z * e0 + d.w * e1;
        }
#pragma unroll
        for (int o = 1; o <= 2; o <<= 1) {
            va0 += __shfl_xor_sync(0xffffffffu, va0, o);
            va1 += __shfl_xor_sync(0xffffffffu, va1, o);
            vd0 += __shfl_xor_sync(0xffffffffu, vd0, o);
            vd1 += __shfl_xor_sync(0xffffffffu, vd1, o);
        }
        if (tq == 0) {
            int lr = wm * 32 + mt * 16 + gq;
            sAls[lr][wn] = va0; sAls[lr + 8][wn] = va1;
            sAld[lr][wn] = vd0; sAld[lr + 8][wn] = vd1;
        }
    }
    __syncthreads();
    if (tid < 128) {
        int gr = bm + tid;
        if (gr < M) {
            als[(size_t)gr * HSTR + head] = sAls[tid][0] + sAls[tid][1];
            ald[(size_t)gr * HSTR + head] = sAld[tid][0] + sAld[tid][1];
        }
    }
}

__device__ __forceinline__ float leaky(float a) { return (a > 0.f) ? a : NEG * a; }
__device__ __forceinline__ float4 leakyadd4(float4 a, float4 b) {
    return make_float4(leaky(a.x + b.x), leaky(a.y + b.y), leaky(a.z + b.z), leaky(a.w + b.w));
}
__device__ __forceinline__ float sel4(float4 v, int h) {
    return (h == 0) ? v.x : (h == 1) ? v.y : (h == 2) ? v.z : v.w;
}

// ====== fused softmax+gather (layers 1-2): warp/dst, weights in registers ======
__global__ void k_fgather256(const __nv_bfloat16* __restrict__ hb,
                             const float4* __restrict__ als4,
                             const float4* __restrict__ ald4,
                             const float* __restrict__ bias,
                             __nv_bfloat16* __restrict__ out) {
    int w = (blockIdx.x * blockDim.x + threadIdx.x) >> 5;
    if (w >= NN) return;
    int lane = threadIdx.x & 31;
    int head = lane >> 3;
    int s0 = g_off[w], s1 = g_off[w + 1];
    int deg = s1 - s0;
    float4 ad = ald4[w];

    // ---- pass 1 (lane-parallel): leaky alphas, max, exp weights in regs ----
    int idx0 = (lane < deg)      ? g_csr[s0 + lane]      : -1;
    int idx1 = (32 + lane < deg) ? g_csr[s0 + 32 + lane] : -1;
    float4 a0 = make_float4(-1e30f, -1e30f, -1e30f, -1e30f);
    float4 a1 = a0;
    if (idx0 >= 0) a0 = leakyadd4(als4[idx0], ad);
    if (idx1 >= 0) a1 = leakyadd4(als4[idx1], ad);
    float4 m;
    m.x = fmaxf(a0.x, a1.x); m.y = fmaxf(a0.y, a1.y);
    m.z = fmaxf(a0.z, a1.z); m.w = fmaxf(a0.w, a1.w);
    for (int i = s0 + 64 + lane; i < s1; i += 32) {
        float4 t = leakyadd4(als4[g_csr[i]], ad);
        m.x = fmaxf(m.x, t.x); m.y = fmaxf(m.y, t.y);
        m.z = fmaxf(m.z, t.z); m.w = fmaxf(m.w, t.w);
    }
#pragma unroll
    for (int o = 16; o >= 1; o >>= 1) {
        m.x = fmaxf(m.x, __shfl_xor_sync(0xffffffffu, m.x, o));
        m.y = fmaxf(m.y, __shfl_xor_sync(0xffffffffu, m.y, o));
        m.z = fmaxf(m.z, __shfl_xor_sync(0xffffffffu, m.z, o));
        m.w = fmaxf(m.w, __shfl_xor_sync(0xffffffffu, m.w, o));
    }
    float4 e0 = make_float4(0.f, 0.f, 0.f, 0.f), e1 = e0;
    if (idx0 >= 0) e0 = make_float4(__expf(a0.x - m.x), __expf(a0.y - m.y),
                                    __expf(a0.z - m.z), __expf(a0.w - m.w));
    if (idx1 >= 0) e1 = make_float4(__expf(a1.x - m.x), __expf(a1.y - m.y),
                                    __expf(a1.z - m.z), __expf(a1.w - m.w));
    float4 den = make_float4(e0.x + e1.x, e0.y + e1.y, e0.z + e1.z, e0.w + e1.w);
    for (int i = s0 + 64 + lane; i < s1; i += 32) {
        float4 t = leakyadd4(als4[g_csr[i]], ad);
        den.x += __expf(t.x - m.x); den.y += __expf(t.y - m.y);
        den.z += __expf(t.z - m.z); den.w += __expf(t.w - m.w);
    }
#pragma unroll
    for (int o = 16; o >= 1; o >>= 1) {
        den.x += __shfl_xor_sync(0xffffffffu, den.x, o);
        den.y += __shfl_xor_sync(0xffffffffu, den.y, o);
        den.z += __shfl_xor_sync(0xffffffffu, den.z, o);
        den.w += __shfl_xor_sync(0xffffffffu, den.w, o);
    }
    float rd  = 1.f / sel4(den, head);
    float mh  = sel4(m, head);
    float adh = sel4(ad, head);

    // ---- pass 2 (serial over edges): shfl index+weight, gather h rows ----
    float acc[8] = {0.f, 0.f, 0.f, 0.f, 0.f, 0.f, 0.f, 0.f};
    int d1 = (deg < 32) ? deg : 32;
    int j = 0;
    for (; j + 2 <= d1; j += 2) {
        int sA = __shfl_sync(0xffffffffu, idx0, j);
        int sB = __shfl_sync(0xffffffffu, idx0, j + 1);
        float ax = __shfl_sync(0xffffffffu, e0.x, j), ay = __shfl_sync(0xffffffffu, e0.y, j);
        float az = __shfl_sync(0xffffffffu, e0.z, j), aw = __shfl_sync(0xffffffffu, e0.w, j);
        float bx = __shfl_sync(0xffffffffu, e0.x, j + 1), by = __shfl_sync(0xffffffffu, e0.y, j + 1);
        float bz = __shfl_sync(0xffffffffu, e0.z, j + 1), bw = __shfl_sync(0xffffffffu, e0.w, j + 1);
        float wA = (head == 0) ? ax : (head == 1) ? ay : (head == 2) ? az : aw;
        float wB = (head == 0) ? bx : (head == 1) ? by : (head == 2) ? bz : bw;
        uint4 uA = *(const uint4*)(hb + (size_t)sA * HC + lane * 8);
        uint4 uB = *(const uint4*)(hb + (size_t)sB * HC + lane * 8);
        float2 f0 = __bfloat1622float2(*(__nv_bfloat162*)&uA.x);
        float2 f1 = __bfloat1622float2(*(__nv_bfloat162*)&uA.y);
        float2 f2 = __bfloat1622float2(*(__nv_bfloat162*)&uA.z);
        float2 f3 = __bfloat1622float2(*(__nv_bfloat162*)&uA.w);
        acc[0] += wA * f0.x; acc[1] += wA * f0.y;
        acc[2] += wA * f1.x; acc[3] += wA * f1.y;
        acc[4] += wA * f2.x; acc[5] += wA * f2.y;
        acc[6] += wA * f3.x; acc[7] += wA * f3.y;
        float2 h0 = __bfloat1622float2(*(__nv_bfloat162*)&uB.x);
        float2 h1 = __bfloat1622float2(*(__nv_bfloat162*)&uB.y);
        float2 h2 = __bfloat1622float2(*(__nv_bfloat162*)&uB.z);
        float2 h3 = __bfloat1622float2(*(__nv_bfloat162*)&uB.w);
        acc[0] += wB * h0.x; acc[1] += wB * h0.y;
        acc[2] += wB * h1.x; acc[3] += wB * h1.y;
        acc[4] += wB * h2.x; acc[5] += wB * h2.y;
        acc[6] += wB * h3.x; acc[7] += wB * h3.y;
    }
    for (; j < d1; j++) {
        int s = __shfl_sync(0xffffffffu, idx0, j);
        float ax = __shfl_sync(0xffffffffu, e0.x, j), ay = __shfl_sync(0xffffffffu, e0.y, j);
        float az = __shfl_sync(0xffffffffu, e0.z, j), aw = __shfl_sync(0xffffffffu, e0.w, j);
        float wt = (head == 0) ? ax : (head == 1) ? ay : (head == 2) ? az : aw;
        uint4 u = *(const uint4*)(hb + (size_t)s * HC + lane * 8);
        float2 f0 = __bfloat1622float2(*(__nv_bfloat162*)&u.x);
        float2 f1 = __bfloat1622float2(*(__nv_bfloat162*)&u.y);
        float2 f2 = __bfloat1622float2(*(__nv_bfloat162*)&u.z);
        float2 f3 = __bfloat1622float2(*(__nv_bfloat162*)&u.w);
        acc[0] += wt * f0.x; acc[1] += wt * f0.y;
        acc[2] += wt * f1.x; acc[3] += wt * f1.y;
        acc[4] += wt * f2.x; acc[5] += wt * f2.y;
        acc[6] += wt * f3.x; acc[7] += wt * f3.y;
    }
    int d2 = (deg < 64) ? deg : 64;
    for (j = 32; j < d2; j++) {
        int s = __shfl_sync(0xffffffffu, idx1, j - 32);
        float ax = __shfl_sync(0xffffffffu, e1.x, j - 32), ay = __shfl_sync(0xffffffffu, e1.y, j - 32);
        float az = __shfl_sync(0xffffffffu, e1.z, j - 32), aw = __shfl_sync(0xffffffffu, e1.w, j - 32);
        float wt = (head == 0) ? ax : (head == 1) ? ay : (head == 2) ? az : aw;
        uint4 u = *(const uint4*)(hb + (size_t)s * HC + lane * 8);
        float2 f0 = __bfloat1622float2(*(__nv_bfloat162*)&u.x);
        float2 f1 = __bfloat1622float2(*(__nv_bfloat162*)&u.y);
        float2 f2 = __bfloat1622float2(*(__nv_bfloat162*)&u.z);
        float2 f3 = __bfloat1622float2(*(__nv_bfloat162*)&u.w);
        acc[0] += wt * f0.x; acc[1] += wt * f0.y;
        acc[2] += wt * f1.x; acc[3] += wt * f1.y;
        acc[4] += wt * f2.x; acc[5] += wt * f2.y;
        acc[6] += wt * f3.x; acc[7] += wt * f3.y;
    }
    for (j = 64; j < deg; j++) {          // ultra-rare tail: recompute
        int s = g_csr[s0 + j];
        const float* alp = (const float*)(als4 + s);
        float wt = __expf(leaky(alp[head] + adh) - mh);
        uint4 u = *(const uint4*)(hb + (size_t)s * HC + lane * 8);
        float2 f0 = __bfloat1622float2(*(__nv_bfloat162*)&u.x);
        float2 f1 = __bfloat1622float2(*(__nv_bfloat162*)&u.y);
        float2 f2 = __bfloat1622float2(*(__nv_bfloat162*)&u.z);
        float2 f3 = __bfloat1622float2(*(__nv_bfloat162*)&u.w);
        acc[0] += wt * f0.x; acc[1] += wt * f0.y;
        acc[2] += wt * f1.x; acc[3] += wt * f1.y;
        acc[4] += wt * f2.x; acc[5] += wt * f2.y;
        acc[6] += wt * f3.x; acc[7] += wt * f3.y;
    }

    float4 b0 = *(const float4*)(bias + lane * 8);
    float4 b1 = *(const float4*)(bias + lane * 8 + 4);
    float v[8];
    v[0] = fmaxf(acc[0] * rd + b0.x, 0.f); v[1] = fmaxf(acc[1] * rd + b0.y, 0.f);
    v[2] = fmaxf(acc[2] * rd + b0.z, 0.f); v[3] = fmaxf(acc[3] * rd + b0.w, 0.f);
    v[4] = fmaxf(acc[4] * rd + b1.x, 0.f); v[5] = fmaxf(acc[5] * rd + b1.y, 0.f);
    v[6] = fmaxf(acc[6] * rd + b1.z, 0.f); v[7] = fmaxf(acc[7] * rd + b1.w, 0.f);
    uint4 u;
    *(__nv_bfloat162*)&u.x = __float22bfloat162_rn(make_float2(v[0], v[1]));
    *(__nv_bfloat162*)&u.y = __float22bfloat162_rn(make_float2(v[2], v[3]));
    *(__nv_bfloat162*)&u.z = __float22bfloat162_rn(make_float2(v[4], v[5]));
    *(__nv_bfloat162*)&u.w = __float22bfloat162_rn(make_float2(v[6], v[7]));
    *(uint4*)(out + (size_t)w * HC + lane * 8) = u;
}

// ====== fused softmax+gather+log_softmax (layer 3, H=1, fp32 h) ======
__global__ void k_fgather40(const float* __restrict__ h,
                            const float* __restrict__ als,
                            const float* __restrict__ ald,
                            const float* __restrict__ bias,
                            float* __restrict__ out) {
    int w = (blockIdx.x * blockDim.x + threadIdx.x) >> 5;
    if (w >= NN) return;
    int lane = threadIdx.x & 31;
    int s0 = g_off[w], s1 = g_off[w + 1];
    int deg = s1 - s0;
    float ad = ald[w];

    int idx0 = (lane < deg)      ? g_csr[s0 + lane]      : -1;
    int idx1 = (32 + lane < deg) ? g_csr[s0 + 32 + lane] : -1;
    float a0v = (idx0 >= 0) ? leaky(als[idx0] + ad) : -1e30f;
    float a1v = (idx1 >= 0) ? leaky(als[idx1] + ad) : -1e30f;
    float m = fmaxf(a0v, a1v);
    for (int i = s0 + 64 + lane; i < s1; i += 32)
        m = fmaxf(m, leaky(als[g_csr[i]] + ad));
#pragma unroll
    for (int o = 16; o >= 1; o >>= 1) m = fmaxf(m, __shfl_xor_sync(0xffffffffu, m, o));
    float e0v = (idx0 >= 0) ? __expf(a0v - m) : 0.f;
    float e1v = (idx1 >= 0) ? __expf(a1v - m) : 0.f;
    float den = e0v + e1v;
    for (int i = s0 + 64 + lane; i < s1; i += 32)
        den += __expf(leaky(als[g_csr[i]] + ad) - m);
#pragma unroll
    for (int o = 16; o >= 1; o >>= 1) den += __shfl_xor_sync(0xffffffffu, den, o);
    float rd = 1.f / den;

    float a0 = 0.f, a1 = 0.f;
    int d1 = (deg < 32) ? deg : 32;
    for (int j = 0; j < d1; j++) {
        int s = __shfl_sync(0xffffffffu, idx0, j);
        float wt = __shfl_sync(0xffffffffu, e0v, j);
        const float* hr = h + (size_t)s * OUTC;
        a0 += wt * hr[lane];
        if (lane < 8) a1 += wt * hr[32 + lane];
    }
    int d2 = (deg < 64) ? deg : 64;
    for (int j = 32; j < d2; j++) {
        int s = __shfl_sync(0xffffffffu, idx1, j - 32);
        float wt = __shfl_sync(0xffffffffu, e1v, j - 32);
        const float* hr = h + (size_t)s * OUTC;
        a0 += wt * hr[lane];
        if (lane < 8) a1 += wt * hr[32 + lane];
    }
    for (int j = 64; j < deg; j++) {
        int s = g_csr[s0 + j];
        float wt = __expf(leaky(als[s] + ad) - m);
        const float* hr = h + (size_t)s * OUTC;
        a0 += wt * hr[lane];
        if (lane < 8) a1 += wt * hr[32 + lane];
    }

    float v0 = a0 * rd + bias[lane];
    float v1 = (lane < 8) ? (a1 * rd + bias[32 + lane]) : -1e30f;
    float mx = fmaxf(v0, v1);
#pragma unroll
    for (int o = 16; o >= 1; o >>= 1) mx = fmaxf(mx, __shfl_xor_sync(0xffffffffu, mx, o));
    float se = __expf(v0 - mx) + ((lane < 8) ? __expf(v1 - mx) : 0.f);
#pragma unroll
    for (int o = 16; o >= 1; o >>= 1) se += __shfl_xor_sync(0xffffffffu, se, o);
    float lse = mx + __logf(se);
    float* orow = out + (size_t)w * OUTC;
    orow[lane] = v0 - lse;
    if (lane < 8) orow[32 + lane] = v1 - lse;
}

// ---------------- launch ----------------
extern "C" void kernel_launch(void* const* d_in, const int* in_sizes, int n_in,
                              void* d_out, int out_size) {
    const float* x   = (const float*)d_in[0];
    const void*  ei  = d_in[1];
    const float* W1  = (const float*)d_in[2];
    const float* as1 = (const float*)d_in[3];
    const float* ad1 = (const float*)d_in[4];
    const float* b1  = (const float*)d_in[5];
    const float* W2  = (const float*)d_in[6];
    const float* as2 = (const float*)d_in[7];
    const float* ad2 = (const float*)d_in[8];
    const float* b2  = (const float*)d_in[9];
    const float* W3  = (const float*)d_in[10];
    const float* as3 = (const float*)d_in[11];
    const float* ad3 = (const float*)d_in[12];
    const float* b3  = (const float*)d_in[13];
    float* out = (float*)d_out;

    __nv_bfloat16 *xh, *bufHh, *bufAh;
    float *bufH3, *als, *ald;
    void *degp, *curp;
    cudaGetSymbolAddress((void**)&xh,    g_xh);
    cudaGetSymbolAddress((void**)&bufHh, g_bufHh);
    cudaGetSymbolAddress((void**)&bufAh, g_bufAh);
    cudaGetSymbolAddress((void**)&bufH3, g_bufH3);
    cudaGetSymbolAddress((void**)&als,   g_als);
    cudaGetSymbolAddress((void**)&ald,   g_ald);
    cudaGetSymbolAddress(&degp, g_deg);
    cudaGetSymbolAddress(&curp, g_cur);

    const int TB = 256;
    int warpBlocks = (NN * 32 + TB - 1) / TB;
    int edgeBlocks = (ET + TB - 1) / TB;
    int scanBlocks = (NN + SB - 1) / SB;

    // ---- prep + CSR build ----
    cudaMemsetAsync(degp, 0, NN * sizeof(int));
    cudaMemsetAsync(curp, 0, NN * sizeof(int));
    k_detect<<<1, 256>>>((const int*)ei);
    k_histcvt<<<edgeBlocks, TB>>>(ei, x, xh);
    k_scan1<<<scanBlocks, SB>>>();
    k_scan3<<<scanBlocks, SB>>>(scanBlocks);
    k_scatter<<<edgeBlocks, TB>>>(ei);

    dim3 g1(4, (NN + 127) / 128);
    dim3 g3(1, (NN + 127) / 128);

    // ---- Layer 1 ----
    k_gemmb<HC, 4, __nv_bfloat16><<<g1, 256>>>(xh, W1, bufHh, as1, ad1, als, ald, NN, INC);
    k_fgather256<<<warpBlocks, TB>>>(bufHh, (const float4*)als, (const float4*)ald, b1, bufAh);

    // ---- Layer 2 ----
    k_gemmb<HC, 4, __nv_bfloat16><<<g1, 256>>>(bufAh, W2, bufHh, as2, ad2, als, ald, NN, HC);
    k_fgather256<<<warpBlocks, TB>>>(bufHh, (const float4*)als, (const float4*)ald, b2, bufAh);

    // ---- Layer 3 ----
    k_gemmb<OUTC, 1, float><<<g3, 256>>>(bufAh, W3, bufH3, as3, ad3, als, ald, NN, HC);
    k_fgather40<<<warpBlocks, TB>>>(bufH3, als, ald, b3, out);
}

// round 8
// speedup vs baseline: 1.0276x; 1.0276x over previous
#include <cuda_runtime.h>
#include <cuda_bf16.h>
#include <math.h>
#include <stdint.h>

#define NN   50000
#define EE   800000
#define ET   (EE + NN)    // edges + self loops = 850000
#define INC  128
#define HC   256          // HEADS*HID
#define OUTC 40
#define NEG  0.2f

// ---------------- device scratch (no allocations allowed) ----------------
__device__ __nv_bfloat16  g_xh[(size_t)NN * INC];    // bf16 copy of x
__device__ __nv_bfloat16  g_bufHh[(size_t)NN * HC];  // bf16 h (GEMM out, layers 1-2)
__device__ __nv_bfloat16  g_bufAh[(size_t)NN * HC];  // bf16 aggregated (next GEMM in)
__device__ float          g_bufH3[(size_t)NN * OUTC];// fp32 h (layer 3)
__device__ __nv_bfloat16  g_w1h[INC * HC];           // bf16 weights
__device__ __nv_bfloat16  g_w2h[HC * HC];
__device__ __nv_bfloat16  g_w3h[HC * OUTC];
__device__ float g_als[(size_t)NN * 4];
__device__ float g_ald[(size_t)NN * 4];
__device__ float g_attn[(size_t)ET * 4];    // per-edge attention scratch
__device__ float g_rden[(size_t)NN * 4];
__device__ int   g_off[NN + 1];
__device__ int   g_cur[NN];
__device__ int   g_deg[NN];
__device__ int   g_csr[ET];
__device__ volatile unsigned long long g_chain[64];
__device__ int   g_i64flag;

__device__ __forceinline__ int edge_at(const void* ei, int f, long long pos) {
    return f ? (int)(((const long long*)ei)[pos]) : ((const int*)ei)[pos];
}

// ---------------- edge dtype detection ----------------
__global__ void k_detect(const int* ei32) {
    __shared__ int sAny[8];
    int bad = 0;
    for (int j = threadIdx.x; j < 4096; j += blockDim.x)
        if (ei32[2 * j + 1] != 0) bad = 1;
    unsigned any = __ballot_sync(0xffffffffu, bad);
    if ((threadIdx.x & 31) == 0) sAny[threadIdx.x >> 5] = (any != 0);
    __syncthreads();
    if (threadIdx.x == 0) {
        int t = 0;
        for (int w = 0; w < (int)(blockDim.x >> 5); w++) t |= sAny[w];
        g_i64flag = t ? 0 : 1;
    }
}

// ------- fused: dst histogram + x->bf16 + W1/W2/W3 -> bf16 ----------------
__device__ __forceinline__ void cvt8(const float* src, __nv_bfloat16* dst) {
    const float4* p = (const float4*)src;
    float4 a = p[0], b = p[1];
    uint4 u;
    *(__nv_bfloat162*)&u.x = __float22bfloat162_rn(make_float2(a.x, a.y));
    *(__nv_bfloat162*)&u.y = __float22bfloat162_rn(make_float2(a.z, a.w));
    *(__nv_bfloat162*)&u.z = __float22bfloat162_rn(make_float2(b.x, b.y));
    *(__nv_bfloat162*)&u.w = __float22bfloat162_rn(make_float2(b.z, b.w));
    *(uint4*)dst = u;
}

__global__ void k_histcvt(const void* ei, const float* __restrict__ x,
                          const float* __restrict__ W1, const float* __restrict__ W2,
                          const float* __restrict__ W3) {
    int i = blockIdx.x * blockDim.x + threadIdx.x;
    if (i < NN * INC / 8) cvt8(x + (size_t)i * 8, g_xh + (size_t)i * 8);
    int base = NN * INC / 8;
    int j = i - base;
    if (j >= 0) {
        if (j < (INC * HC) / 8) cvt8(W1 + j * 8, g_w1h + j * 8);
        else if ((j -= (INC * HC) / 8) < (HC * HC) / 8) cvt8(W2 + j * 8, g_w2h + j * 8);
        else if ((j -= (HC * HC) / 8) < (HC * OUTC) / 8) cvt8(W3 + j * 8, g_w3h + j * 8);
    }
    if (i < ET) {
        int f = g_i64flag;
        int d = (i < EE) ? edge_at(ei, f, (long long)EE + i) : (i - EE);
        atomicAdd(&g_deg[d], 1);
    }
}

#define SB 1024
// single-kernel chained scan (decoupled lookback via packed {sum,flag} word)
__global__ void k_scan() {
    __shared__ int sh[SB];
    __shared__ int sPre;
    int b = blockIdx.x;
    int g = b * SB + threadIdx.x;
    int v = (g < NN) ? g_deg[g] : 0;
    sh[threadIdx.x] = v;
    __syncthreads();
    for (int o = 1; o < SB; o <<= 1) {
        int t = (threadIdx.x >= o) ? sh[threadIdx.x - o] : 0;
        __syncthreads();
        sh[threadIdx.x] += t;
        __syncthreads();
    }
    if (threadIdx.x == SB - 1) {
        int total = sh[SB - 1];
        int prefix = 0;
        if (b > 0) {
            unsigned long long c;
            do { c = g_chain[b - 1]; } while (!(c & 1ull));
            prefix = (int)(c >> 32);
        }
        g_chain[b] = (((unsigned long long)(unsigned)(prefix + total)) << 32) | 1ull;
        sPre = prefix;
    }
    __syncthreads();
    int prefix = sPre;
    if (g < NN) g_off[g] = prefix + sh[threadIdx.x] - v;   // exclusive
    if (g == 0) g_off[NN] = ET;
}

__global__ void k_scatter(const void* ei) {
    int e = blockIdx.x * blockDim.x + threadIdx.x;
    if (e >= ET) return;
    int f = g_i64flag;
    int s, d;
    if (e < EE) { s = edge_at(ei, f, e); d = edge_at(ei, f, (long long)EE + e); }
    else        { s = d = e - EE; }
    int p = g_off[d] + atomicAdd(&g_cur[d], 1);
    g_csr[p] = s;
}

// ---------------- bf16 MMA helpers ----------------
__device__ __forceinline__ void ldsm4(uint32_t* r, uint32_t addr) {
    asm volatile("ldmatrix.sync.aligned.m8n8.x4.shared.b16 {%0,%1,%2,%3}, [%4];"
                 : "=r"(r[0]), "=r"(r[1]), "=r"(r[2]), "=r"(r[3]) : "r"(addr));
}

__device__ __forceinline__ void mma_bf16(float4& d, const uint32_t* a, const uint32_t* b) {
    asm volatile(
        "mma.sync.aligned.m16n8k16.row.col.f32.bf16.bf16.f32 "
        "{%0,%1,%2,%3}, {%4,%5,%6,%7}, {%8,%9}, {%0,%1,%2,%3};\n"
        : "+f"(d.x), "+f"(d.y), "+f"(d.z), "+f"(d.w)
        : "r"(a[0]), "r"(a[1]), "r"(a[2]), "r"(a[3]), "r"(b[0]), "r"(b[1]));
}

__device__ __forceinline__ void store_c(__nv_bfloat16* C, size_t r, int stride, int col,
                                        float x, float y, int ncq) {
    *(__nv_bfloat162*)(C + r * stride + col) = __float22bfloat162_rn(make_float2(x, y));
}
__device__ __forceinline__ void store_c(float* C, size_t r, int stride, int col,
                                        float x, float y, int ncq) {
    if (col < ncq) *(float2*)(C + r * stride + col) = make_float2(x, y);
}

#define LDA 40  // padded smem row stride in bf16 elems

// ============ bf16 GEMM + fused attention projections =====================
// A bf16 [M,K], Wh bf16 [K,NCQ]; C + per-head als/ald reductions in epilogue.
template<int NCQ, int HSTR, typename CT>
__global__ __launch_bounds__(256) void k_gemmb(const __nv_bfloat16* __restrict__ A,
                                               const __nv_bfloat16* __restrict__ Wh,
                                               CT* __restrict__ C,
                                               const float* __restrict__ asv,
                                               const float* __restrict__ adv,
                                               float* __restrict__ als,
                                               float* __restrict__ ald,
                                               int M, int K) {
    __shared__ __nv_bfloat16 As[128 * LDA];
    __shared__ __nv_bfloat16 Bs[64 * LDA];
    __shared__ float sAls[128][2];
    __shared__ float sAld[128][2];
    int tid = threadIdx.x;
    int lane = tid & 31, warp = tid >> 5;
    int wm = warp & 3, wn = warp >> 2;
    int bm = blockIdx.y * 128, bn = blockIdx.x * 64;
    int head = blockIdx.x;

    float4 acc[2][4];
#pragma unroll
    for (int mt = 0; mt < 2; mt++)
#pragma unroll
        for (int nt = 0; nt < 4; nt++) acc[mt][nt] = make_float4(0.f, 0.f, 0.f, 0.f);

    uint4 ra[2];   // staged A: 8 bf16/thread x2
    uint2 rbh[2];  // staged W: 4 bf16/thread x2

#pragma unroll
    for (int i = 0; i < 2; i++) {
        int idx = i * 256 + tid;
        int row = idx >> 2, c8 = idx & 3;
        int gr = bm + row;
        ra[i] = (gr < M) ? *(const uint4*)(A + (size_t)gr * K + c8 * 8)
                         : make_uint4(0u, 0u, 0u, 0u);
    }
#pragma unroll
    for (int i = 0; i < 2; i++) {
        int idx = i * 256 + tid;
        int kr = idx >> 4, nc4 = idx & 15;
        int gc = bn + nc4 * 4;
        rbh[i] = (NCQ >= 64 || gc + 3 < NCQ)
               ? *(const uint2*)(Wh + (size_t)kr * NCQ + gc)
               : make_uint2(0u, 0u);
    }

    uint32_t smA = (uint32_t)__cvta_generic_to_shared(As);
    uint32_t smB = (uint32_t)__cvta_generic_to_shared(Bs);

    for (int k0 = 0; k0 < K; k0 += 32) {
#pragma unroll
        for (int i = 0; i < 2; i++) {
            int idx = i * 256 + tid;
            int row = idx >> 2, c8 = idx & 3;
            *(uint4*)(As + row * LDA + c8 * 8) = ra[i];
        }
#pragma unroll
        for (int i = 0; i < 2; i++) {
            int idx = i * 256 + tid;
            int kr = idx >> 4, nc4 = idx & 15;
            const __nv_bfloat16* pv = (const __nv_bfloat16*)&rbh[i];
            Bs[(nc4 * 4 + 0) * LDA + kr] = pv[0];
            Bs[(nc4 * 4 + 1) * LDA + kr] = pv[1];
            Bs[(nc4 * 4 + 2) * LDA + kr] = pv[2];
            Bs[(nc4 * 4 + 3) * LDA + kr] = pv[3];
        }
        __syncthreads();

        int kn = k0 + 32;
        if (kn < K) {
#pragma unroll
            for (int i = 0; i < 2; i++) {
                int idx = i * 256 + tid;
                int row = idx >> 2, c8 = idx & 3;
                int gr = bm + row;
                ra[i] = (gr < M) ? *(const uint4*)(A + (size_t)gr * K + kn + c8 * 8)
                                 : make_uint4(0u, 0u, 0u, 0u);
            }
#pragma unroll
            for (int i = 0; i < 2; i++) {
                int idx = i * 256 + tid;
                int kr = idx >> 4, nc4 = idx & 15;
                int gc = bn + nc4 * 4;
                rbh[i] = (NCQ >= 64 || gc + 3 < NCQ)
                       ? *(const uint2*)(Wh + (size_t)(kn + kr) * NCQ + gc)
                       : make_uint2(0u, 0u);
            }
        }

#pragma unroll
        for (int ks = 0; ks < 2; ks++) {
            int kk = ks * 16;
            uint32_t afr[2][4], bfr[4][2];
#pragma unroll
            for (int mt = 0; mt < 2; mt++) {
                int mrow = wm * 32 + mt * 16 + (lane & 15);
                int kc = kk + ((lane >> 4) << 3);
                ldsm4(afr[mt], smA + (uint32_t)(mrow * LDA + kc) * 2u);
            }
#pragma unroll
            for (int nh = 0; nh < 2; nh++) {
                int nrow = wn * 32 + nh * 16 + ((lane >> 4) << 3) + (lane & 7);
                int kc = kk + (((lane >> 3) & 1) << 3);
                uint32_t tmp[4];
                ldsm4(tmp, smB + (uint32_t)(nrow * LDA + kc) * 2u);
                bfr[nh * 2 + 0][0] = tmp[0]; bfr[nh * 2 + 0][1] = tmp[1];
                bfr[nh * 2 + 1][0] = tmp[2]; bfr[nh * 2 + 1][1] = tmp[3];
            }
#pragma unroll
            for (int mt = 0; mt < 2; mt++)
#pragma unroll
                for (int nt = 0; nt < 4; nt++)
                    mma_bf16(acc[mt][nt], afr[mt], bfr[nt]);
        }
        __syncthreads();
    }

    int gq = lane >> 2, tq = lane & 3;
    const float* asvh = asv + head * 64;
    const float* advh = adv + head * 64;
#pragma unroll
    for (int mt = 0; mt < 2; mt++) {
        float va0 = 0.f, va1 = 0.f, vd0 = 0.f, vd1 = 0.f;
        int r0 = bm + wm * 32 + mt * 16 + gq;
        int r1 = r0 + 8;
#pragma unroll
        for (int nt = 0; nt < 4; nt++) {
            int cl = wn * 32 + nt * 8 + tq * 2;
            float4 d = acc[mt][nt];
            if (r0 < M) store_c(C, (size_t)r0, NCQ, bn + cl, d.x, d.y, NCQ);
            if (r1 < M) store_c(C, (size_t)r1, NCQ, bn + cl, d.z, d.w, NCQ);
            float a0 = (NCQ >= 64 || cl + 0 < NCQ) ? asvh[cl] : 0.f;
            float a1 = (NCQ >= 64 || cl + 1 < NCQ) ? asvh[cl + 1] : 0.f;
            float e0 = (NCQ >= 64 || cl + 0 < NCQ) ? advh[cl] : 0.f;
            float e1 = (NCQ >= 64 || cl + 1 < NCQ) ? advh[cl + 1] : 0.f;
            va0 += d.x * a0 + d.y * a1;
            va1 += d.z * a0 + d.w * a1;
            vd0 += d.x * e0 + d.y * e1;
            vd1 += d.z * e0 + d.w * e1;
        }
#pragma unroll
        for (int o = 1; o <= 2; o <<= 1) {
            va0 += __shfl_xor_sync(0xffffffffu, va0, o);
            va1 += __shfl_xor_sync(0xffffffffu, va1, o);
            vd0 += __shfl_xor_sync(0xffffffffu, vd0, o);
            vd1 += __shfl_xor_sync(0xffffffffu, vd1, o);
        }
        if (tq == 0) {
            int lr = wm * 32 + mt * 16 + gq;
            sAls[lr][wn] = va0; sAls[lr + 8][wn] = va1;
            sAld[lr][wn] = vd0; sAld[lr + 8][wn] = vd1;
        }
    }
    __syncthreads();
    if (tid < 128) {
        int gr = bm + tid;
        if (gr < M) {
            als[(size_t)gr * HSTR + head] = sAls[tid][0] + sAls[tid][1];
            ald[(size_t)gr * HSTR + head] = sAld[tid][0] + sAld[tid][1];
        }
    }
}

// ---------------- warp-per-dst segment softmax (H=4) ----------------
__global__ void k_attnW4(const float4* __restrict__ als4, const float4* __restrict__ ald4,
                         float4* __restrict__ attn4, float4* __restrict__ rden4) {
    int w = (blockIdx.x * blockDim.x + threadIdx.x) >> 5;
    if (w >= NN) return;
    int lane = threadIdx.x & 31;
    int s0 = g_off[w], s1 = g_off[w + 1];
    float4 ad = ald4[w];
    float4 m = make_float4(-1e30f, -1e30f, -1e30f, -1e30f);
    for (int i = s0 + lane; i < s1; i += 32) {
        int s = g_csr[i];
        float4 a = als4[s];
        a.x += ad.x; a.y += ad.y; a.z += ad.z; a.w += ad.w;
        a.x = (a.x > 0.f) ? a.x : NEG * a.x;
        a.y = (a.y > 0.f) ? a.y : NEG * a.y;
        a.z = (a.z > 0.f) ? a.z : NEG * a.z;
        a.w = (a.w > 0.f) ? a.w : NEG * a.w;
        attn4[i] = a;
        m.x = fmaxf(m.x, a.x); m.y = fmaxf(m.y, a.y);
        m.z = fmaxf(m.z, a.z); m.w = fmaxf(m.w, a.w);
    }
#pragma unroll
    for (int o = 16; o >= 1; o >>= 1) {
        m.x = fmaxf(m.x, __shfl_xor_sync(0xffffffffu, m.x, o));
        m.y = fmaxf(m.y, __shfl_xor_sync(0xffffffffu, m.y, o));
        m.z = fmaxf(m.z, __shfl_xor_sync(0xffffffffu, m.z, o));
        m.w = fmaxf(m.w, __shfl_xor_sync(0xffffffffu, m.w, o));
    }
    float4 den = make_float4(0.f, 0.f, 0.f, 0.f);
    for (int i = s0 + lane; i < s1; i += 32) {
        float4 a = attn4[i];
        a.x = __expf(a.x - m.x); a.y = __expf(a.y - m.y);
        a.z = __expf(a.z - m.z); a.w = __expf(a.w - m.w);
        attn4[i] = a;
        den.x += a.x; den.y += a.y; den.z += a.z; den.w += a.w;
    }
#pragma unroll
    for (int o = 16; o >= 1; o >>= 1) {
        den.x += __shfl_xor_sync(0xffffffffu, den.x, o);
        den.y += __shfl_xor_sync(0xffffffffu, den.y, o);
        den.z += __shfl_xor_sync(0xffffffffu, den.z, o);
        den.w += __shfl_xor_sync(0xffffffffu, den.w, o);
    }
    if (lane == 0)
        rden4[w] = make_float4(1.f / den.x, 1.f / den.y, 1.f / den.z, 1.f / den.w);
}

// ---------------- warp-per-dst segment softmax (H=1, layer 3) ----------------
__global__ void k_attnW1(const float* __restrict__ als, const float* __restrict__ ald,
                         float* __restrict__ attn, float* __restrict__ rden) {
    int w = (blockIdx.x * blockDim.x + threadIdx.x) >> 5;
    if (w >= NN) return;
    int lane = threadIdx.x & 31;
    int s0 = g_off[w], s1 = g_off[w + 1];
    float ad = ald[w];
    float m = -1e30f;
    for (int i = s0 + lane; i < s1; i += 32) {
        int s = g_csr[i];
        float a = als[s] + ad;
        a = (a > 0.f) ? a : NEG * a;
        attn[i] = a;
        m = fmaxf(m, a);
    }
#pragma unroll
    for (int o = 16; o >= 1; o >>= 1) m = fmaxf(m, __shfl_xor_sync(0xffffffffu, m, o));
    float den = 0.f;
    for (int i = s0 + lane; i < s1; i += 32) {
        float a = __expf(attn[i] - m);
        attn[i] = a;
        den += a;
    }
#pragma unroll
    for (int o = 16; o >= 1; o >>= 1) den += __shfl_xor_sync(0xffffffffu, den, o);
    if (lane == 0) rden[w] = 1.f / den;
}

// ------- bf16 aggregation gather: warp per dst, 2-edge unrolled, bf16 out -------
__global__ void k_gather256(const __nv_bfloat16* __restrict__ hb,
                            const float* __restrict__ bias,
                            const float* __restrict__ attn, const float* __restrict__ rden,
                            __nv_bfloat16* __restrict__ out) {
    int w = (blockIdx.x * blockDim.x + threadIdx.x) >> 5;
    if (w >= NN) return;
    int lane = threadIdx.x & 31;
    int head = lane >> 3;
    int s0 = g_off[w], s1 = g_off[w + 1];
    float acc[8] = {0.f, 0.f, 0.f, 0.f, 0.f, 0.f, 0.f, 0.f};
    int i = s0;
    for (; i + 2 <= s1; i += 2) {
        int sA = g_csr[i];
        int sB = g_csr[i + 1];
        float wA = attn[(size_t)i * 4 + head];
        float wB = attn[(size_t)(i + 1) * 4 + head];
        uint4 uA = *(const uint4*)(hb + (size_t)sA * HC + lane * 8);
        uint4 uB = *(const uint4*)(hb + (size_t)sB * HC + lane * 8);
        float2 a0 = __bfloat1622float2(*(__nv_bfloat162*)&uA.x);
        float2 a1 = __bfloat1622float2(*(__nv_bfloat162*)&uA.y);
        float2 a2 = __bfloat1622float2(*(__nv_bfloat162*)&uA.z);
        float2 a3 = __bfloat1622float2(*(__nv_bfloat162*)&uA.w);
        acc[0] += wA * a0.x; acc[1] += wA * a0.y;
        acc[2] += wA * a1.x; acc[3] += wA * a1.y;
        acc[4] += wA * a2.x; acc[5] += wA * a2.y;
        acc[6] += wA * a3.x; acc[7] += wA * a3.y;
        float2 b0 = __bfloat1622float2(*(__nv_bfloat162*)&uB.x);
        float2 b1 = __bfloat1622float2(*(__nv_bfloat162*)&uB.y);
        float2 b2 = __bfloat1622float2(*(__nv_bfloat162*)&uB.z);
        float2 b3 = __bfloat1622float2(*(__nv_bfloat162*)&uB.w);
        acc[0] += wB * b0.x; acc[1] += wB * b0.y;
        acc[2] += wB * b1.x; acc[3] += wB * b1.y;
        acc[4] += wB * b2.x; acc[5] += wB * b2.y;
        acc[6] += wB * b3.x; acc[7] += wB * b3.y;
    }
    if (i < s1) {
        int s = g_csr[i];
        float wt = attn[(size_t)i * 4 + head];
        uint4 u = *(const uint4*)(hb + (size_t)s * HC + lane * 8);
        float2 f0 = __bfloat1622float2(*(__nv_bfloat162*)&u.x);
        float2 f1 = __bfloat1622float2(*(__nv_bfloat162*)&u.y);
        float2 f2 = __bfloat1622float2(*(__nv_bfloat162*)&u.z);
        float2 f3 = __bfloat1622float2(*(__nv_bfloat162*)&u.w);
        acc[0] += wt * f0.x; acc[1] += wt * f0.y;
        acc[2] += wt * f1.x; acc[3] += wt * f1.y;
        acc[4] += wt * f2.x; acc[5] += wt * f2.y;
        acc[6] += wt * f3.x; acc[7] += wt * f3.y;
    }
    float rd = rden[w * 4 + head];
    float4 b0 = *(const float4*)(bias + lane * 8);
    float4 b1 = *(const float4*)(bias + lane * 8 + 4);
    float v[8];
    v[0] = fmaxf(acc[0] * rd + b0.x, 0.f); v[1] = fmaxf(acc[1] * rd + b0.y, 0.f);
    v[2] = fmaxf(acc[2] * rd + b0.z, 0.f); v[3] = fmaxf(acc[3] * rd + b0.w, 0.f);
    v[4] = fmaxf(acc[4] * rd + b1.x, 0.f); v[5] = fmaxf(acc[5] * rd + b1.y, 0.f);
    v[6] = fmaxf(acc[6] * rd + b1.z, 0.f); v[7] = fmaxf(acc[7] * rd + b1.w, 0.f);
    uint4 u;
    *(__nv_bfloat162*)&u.x = __float22bfloat162_rn(make_float2(v[0], v[1]));
    *(__nv_bfloat162*)&u.y = __float22bfloat162_rn(make_float2(v[2], v[3]));
    *(__nv_bfloat162*)&u.z = __float22bfloat162_rn(make_float2(v[4], v[5]));
    *(__nv_bfloat162*)&u.w = __float22bfloat162_rn(make_float2(v[6], v[7]));
    *(uint4*)(out + (size_t)w * HC + lane * 8) = u;
}

// layer 3: gather + bias + log_softmax fused (fp32 h), 2-edge unrolled
__global__ void k_gather40(const float* __restrict__ h, const float* __restrict__ bias,
                           const float* __restrict__ attn, const float* __restrict__ rden,
                           float* __restrict__ out) {
    int w = (blockIdx.x * blockDim.x + threadIdx.x) >> 5;
    if (w >= NN) return;
    int lane = threadIdx.x & 31;
    int s0 = g_off[w], s1 = g_off[w + 1];
    float a0 = 0.f, a1 = 0.f;
    int i = s0;
    for (; i + 2 <= s1; i += 2) {
        int sA = g_csr[i];
        int sB = g_csr[i + 1];
        float wA = attn[i];
        float wB = attn[i + 1];
        const float* hA = h + (size_t)sA * OUTC;
        const float* hB = h + (size_t)sB * OUTC;
        float vA0 = hA[lane];
        float vB0 = hB[lane];
        float vA1 = (lane < 8) ? hA[32 + lane] : 0.f;
        float vB1 = (lane < 8) ? hB[32 + lane] : 0.f;
        a0 += wA * vA0 + wB * vB0;
        a1 += wA * vA1 + wB * vB1;
    }
    if (i < s1) {
        int s = g_csr[i];
        float wt = attn[i];
        const float* hr = h + (size_t)s * OUTC;
        a0 += wt * hr[lane];
        if (lane < 8) a1 += wt * hr[32 + lane];
    }
    float rd = rden[w];
    float v0 = a0 * rd + bias[lane];
    float v1 = (lane < 8) ? (a1 * rd + bias[32 + lane]) : -1e30f;
    float mx = fmaxf(v0, v1);
#pragma unroll
    for (int o = 16; o >= 1; o >>= 1) mx = fmaxf(mx, __shfl_xor_sync(0xffffffffu, mx, o));
    float se = __expf(v0 - mx) + ((lane < 8) ? __expf(v1 - mx) : 0.f);
#pragma unroll
    for (int o = 16; o >= 1; o >>= 1) se += __shfl_xor_sync(0xffffffffu, se, o);
    float lse = mx + __logf(se);
    float* orow = out + (size_t)w * OUTC;
    orow[lane] = v0 - lse;
    if (lane < 8) orow[32 + lane] = v1 - lse;
}

// ---------------- launch ----------------
extern "C" void kernel_launch(void* const* d_in, const int* in_sizes, int n_in,
                              void* d_out, int out_size) {
    const float* x   = (const float*)d_in[0];
    const void*  ei  = d_in[1];
    const float* W1  = (const float*)d_in[2];
    const float* as1 = (const float*)d_in[3];
    const float* ad1 = (const float*)d_in[4];
    const float* b1  = (const float*)d_in[5];
    const float* W2  = (const float*)d_in[6];
    const float* as2 = (const float*)d_in[7];
    const float* ad2 = (const float*)d_in[8];
    const float* b2  = (const float*)d_in[9];
    const float* W3  = (const float*)d_in[10];
    const float* as3 = (const float*)d_in[11];
    const float* ad3 = (const float*)d_in[12];
    const float* b3  = (const float*)d_in[13];
    float* out = (float*)d_out;

    __nv_bfloat16 *xh, *bufHh, *bufAh, *w1h, *w2h, *w3h;
    float *bufH3, *als, *ald, *attn, *rden;
    void *degp, *curp, *chainp;
    cudaGetSymbolAddress((void**)&xh,    g_xh);
    cudaGetSymbolAddress((void**)&bufHh, g_bufHh);
    cudaGetSymbolAddress((void**)&bufAh, g_bufAh);
    cudaGetSymbolAddress((void**)&bufH3, g_bufH3);
    cudaGetSymbolAddress((void**)&w1h,   g_w1h);
    cudaGetSymbolAddress((void**)&w2h,   g_w2h);
    cudaGetSymbolAddress((void**)&w3h,   g_w3h);
    cudaGetSymbolAddress((void**)&als,   g_als);
    cudaGetSymbolAddress((void**)&ald,   g_ald);
    cudaGetSymbolAddress((void**)&attn,  g_attn);
    cudaGetSymbolAddress((void**)&rden,  g_rden);
    cudaGetSymbolAddress(&degp,   g_deg);
    cudaGetSymbolAddress(&curp,   g_cur);
    cudaGetSymbolAddress(&chainp, (const void*)g_chain);

    const int TB = 256;
    int warpBlocks = (NN * 32 + TB - 1) / TB;
    int edgeBlocks = (ET + TB - 1) / TB;
    int scanBlocks = (NN + SB - 1) / SB;

    // ---- prep + CSR build ----
    cudaMemsetAsync(degp, 0, NN * sizeof(int));
    cudaMemsetAsync(curp, 0, NN * sizeof(int));
    cudaMemsetAsync(chainp, 0, 64 * sizeof(unsigned long long));
    k_detect<<<1, 256>>>((const int*)ei);
    k_histcvt<<<edgeBlocks, TB>>>(ei, x, W1, W2, W3);
    k_scan<<<scanBlocks, SB>>>();
    k_scatter<<<edgeBlocks, TB>>>(ei);

    dim3 g1(4, (NN + 127) / 128);
    dim3 g3(1, (NN + 127) / 128);

    // ---- Layer 1 ----
    k_gemmb<HC, 4, __nv_bfloat16><<<g1, 256>>>(xh, w1h, bufHh, as1, ad1, als, ald, NN, INC);
    k_attnW4<<<warpBlocks, TB>>>((const float4*)als, (const float4*)ald,
                                 (float4*)attn, (float4*)rden);
    k_gather256<<<warpBlocks, TB>>>(bufHh, b1, attn, rden, bufAh);

    // ---- Layer 2 ----
    k_gemmb<HC, 4, __nv_bfloat16><<<g1, 256>>>(bufAh, w2h, bufHh, as2, ad2, als, ald, NN, HC);
    k_attnW4<<<warpBlocks, TB>>>((const float4*)als, (const float4*)ald,
                                 (float4*)attn, (float4*)rden);
    k_gather256<<<warpBlocks, TB>>>(bufHh, b2, attn, rden, bufAh);

    // ---- Layer 3 ----
    k_gemmb<OUTC, 1, float><<<g3, 256>>>(bufAh, w3h, bufH3, as3, ad3, als, ald, NN, HC);
    k_attnW1<<<warpBlocks, TB>>>(als, ald, attn, rden);
    k_gather40<<<warpBlocks, TB>>>(bufH3, b3, attn, rden, out);
}

// round 10
// speedup vs baseline: 1.1395x; 1.1088x over previous
#include <cuda_runtime.h>
#include <cuda_bf16.h>
#include <math.h>
#include <stdint.h>

#define NN   50000
#define EE   800000
#define ET   (EE + NN)    // edges + self loops = 850000
#define INC  128
#define HC   256          // HEADS*HID
#define OUTC 40
#define NEG  0.2f

// ---------------- device scratch (no allocations allowed) ----------------
__device__ __nv_bfloat16  g_xh[(size_t)NN * INC];    // bf16 copy of x
__device__ __nv_bfloat16  g_bufHh[(size_t)NN * HC];  // bf16 h (GEMM out, layers 1-2)
__device__ __nv_bfloat16  g_bufAh[(size_t)NN * HC];  // bf16 aggregated (next GEMM in)
__device__ float          g_bufH3[(size_t)NN * OUTC];// fp32 h (layer 3)
__device__ float g_als[(size_t)NN * 4];
__device__ float g_ald[(size_t)NN * 4];
__device__ float g_attn[(size_t)ET * 4];    // per-edge attention scratch
__device__ int   g_off[NN + 1];
__device__ int   g_cur[NN];
__device__ int   g_deg[NN];
__device__ int   g_csr[ET];
__device__ int   g_bsum[64];
__device__ int   g_i64flag;

__device__ __forceinline__ int edge_at(const void* ei, int f, long long pos) {
    return f ? (int)(((const long long*)ei)[pos]) : ((const int*)ei)[pos];
}

// ---------------- prep: dtype detect + zero counters + x->bf16 ------------
__global__ void k_prep(const float* __restrict__ x, __nv_bfloat16* __restrict__ xh,
                       const int* ei32, int n8) {
    int i = blockIdx.x * blockDim.x + threadIdx.x;
    if (i < n8) {
        const float4* p = (const float4*)(x + (size_t)i * 8);
        float4 a = p[0], b = p[1];
        uint4 u;
        *(__nv_bfloat162*)&u.x = __float22bfloat162_rn(make_float2(a.x, a.y));
        *(__nv_bfloat162*)&u.y = __float22bfloat162_rn(make_float2(a.z, a.w));
        *(__nv_bfloat162*)&u.z = __float22bfloat162_rn(make_float2(b.x, b.y));
        *(__nv_bfloat162*)&u.w = __float22bfloat162_rn(make_float2(b.z, b.w));
        *(uint4*)(xh + (size_t)i * 8) = u;
    }
    if (i < NN) { g_deg[i] = 0; g_cur[i] = 0; }
    if (blockIdx.x == 0) {
        int bad = 0;
        for (int j = threadIdx.x; j < 4096; j += blockDim.x)
            if (ei32[2 * j + 1] != 0) bad = 1;
        unsigned any = __ballot_sync(0xffffffffu, bad);
        __shared__ int sAny[8];
        if ((threadIdx.x & 31) == 0) sAny[threadIdx.x >> 5] = (any != 0);
        __syncthreads();
        if (threadIdx.x == 0) {
            int t = 0;
            for (int w = 0; w < (int)(blockDim.x >> 5); w++) t |= sAny[w];
            g_i64flag = t ? 0 : 1;
        }
    }
}

// ---------------- CSR build ----------------
__global__ void k_hist(const void* ei) {
    int e = blockIdx.x * blockDim.x + threadIdx.x;
    if (e >= ET) return;
    int f = g_i64flag;
    int d = (e < EE) ? edge_at(ei, f, (long long)EE + e) : (e - EE);
    atomicAdd(&g_deg[d], 1);
}

#define SB 1024
__global__ void k_scan1() {
    __shared__ int sh[SB];
    int g = blockIdx.x * SB + threadIdx.x;
    int v = (g < NN) ? g_deg[g] : 0;
    sh[threadIdx.x] = v;
    __syncthreads();
    for (int o = 1; o < SB; o <<= 1) {
        int t = (threadIdx.x >= o) ? sh[threadIdx.x - o] : 0;
        __syncthreads();
        sh[threadIdx.x] += t;
        __syncthreads();
    }
    if (g < NN) g_off[g] = sh[threadIdx.x] - v;   // exclusive
    if (threadIdx.x == SB - 1) g_bsum[blockIdx.x] = sh[SB - 1];
}
// scan3 computes the block-sum prefix itself
__global__ void k_scan3(int nb) {
    __shared__ int sC[2];
    int t = threadIdx.x;
    if (t < 64) {
        int v = (t < nb && t < (int)blockIdx.x) ? g_bsum[t] : 0;
#pragma unroll
        for (int o = 16; o >= 1; o >>= 1) v += __shfl_xor_sync(0xffffffffu, v, o);
        if ((t & 31) == 0) sC[t >> 5] = v;
    }
    __syncthreads();
    int carry = sC[0] + sC[1];
    int g = blockIdx.x * SB + t;
    if (g < NN) g_off[g] += carry;
    if (g == 0) g_off[NN] = ET;
}

__global__ void k_scatter(const void* ei) {
    int e = blockIdx.x * blockDim.x + threadIdx.x;
    if (e >= ET) return;
    int f = g_i64flag;
    int s, d;
    if (e < EE) { s = edge_at(ei, f, e); d = edge_at(ei, f, (long long)EE + e); }
    else        { s = d = e - EE; }
    int p = g_off[d] + atomicAdd(&g_cur[d], 1);
    g_csr[p] = s;
}

// ---------------- bf16 MMA helpers ----------------
__device__ __forceinline__ void ldsm4(uint32_t* r, uint32_t addr) {
    asm volatile("ldmatrix.sync.aligned.m8n8.x4.shared.b16 {%0,%1,%2,%3}, [%4];"
                 : "=r"(r[0]), "=r"(r[1]), "=r"(r[2]), "=r"(r[3]) : "r"(addr));
}

__device__ __forceinline__ void mma_bf16(float4& d, const uint32_t* a, const uint32_t* b) {
    asm volatile(
        "mma.sync.aligned.m16n8k16.row.col.f32.bf16.bf16.f32 "
        "{%0,%1,%2,%3}, {%4,%5,%6,%7}, {%8,%9}, {%0,%1,%2,%3};\n"
        : "+f"(d.x), "+f"(d.y), "+f"(d.z), "+f"(d.w)
        : "r"(a[0]), "r"(a[1]), "r"(a[2]), "r"(a[3]), "r"(b[0]), "r"(b[1]));
}

__device__ __forceinline__ void store_c(__nv_bfloat16* C, size_t r, int stride, int col,
                                        float x, float y, int ncq) {
    *(__nv_bfloat162*)(C + r * stride + col) = __float22bfloat162_rn(make_float2(x, y));
}
__device__ __forceinline__ void store_c(float* C, size_t r, int stride, int col,
                                        float x, float y, int ncq) {
    if (col < ncq) *(float2*)(C + r * stride + col) = make_float2(x, y);
}

#define LDA 40  // padded smem row stride in bf16 elems

// ============ bf16 GEMM + fused attention projections =====================
template<int NCQ, int HSTR, typename CT>
__global__ __launch_bounds__(256) void k_gemmb(const __nv_bfloat16* __restrict__ A,
                                               const float* __restrict__ W,
                                               CT* __restrict__ C,
                                               const float* __restrict__ asv,
                                               const float* __restrict__ adv,
                                               float* __restrict__ als,
                                               float* __restrict__ ald,
                                               int M, int K) {
    __shared__ __nv_bfloat16 As[128 * LDA];
    __shared__ __nv_bfloat16 Bs[64 * LDA];
    __shared__ float sAls[128][2];
    __shared__ float sAld[128][2];
    int tid = threadIdx.x;
    int lane = tid & 31, warp = tid >> 5;
    int wm = warp & 3, wn = warp >> 2;
    int bm = blockIdx.y * 128, bn = blockIdx.x * 64;
    int head = blockIdx.x;

    float4 acc[2][4];
#pragma unroll
    for (int mt = 0; mt < 2; mt++)
#pragma unroll
        for (int nt = 0; nt < 4; nt++) acc[mt][nt] = make_float4(0.f, 0.f, 0.f, 0.f);

    uint4  ra[2];
    float4 rb[2];

#pragma unroll
    for (int i = 0; i < 2; i++) {
        int idx = i * 256 + tid;
        int row = idx >> 2, c8 = idx & 3;
        int gr = bm + row;
        ra[i] = (gr < M) ? *(const uint4*)(A + (size_t)gr * K + c8 * 8)
                         : make_uint4(0u, 0u, 0u, 0u);
    }
#pragma unroll
    for (int i = 0; i < 2; i++) {
        int idx = i * 256 + tid;
        int kr = idx >> 4, nc4 = idx & 15;
        int gc = bn + nc4 * 4;
        const float* wp = W + (size_t)kr * NCQ + gc;
        float4 v = make_float4(0.f, 0.f, 0.f, 0.f);
        if (NCQ >= 64 || gc + 3 < NCQ) {
            if (NCQ >= 64 || gc < NCQ) v = *(const float4*)wp;
        } else {
            if (gc + 0 < NCQ) v.x = wp[0];
            if (gc + 1 < NCQ) v.y = wp[1];
            if (gc + 2 < NCQ) v.z = wp[2];
            if (gc + 3 < NCQ) v.w = wp[3];
        }
        rb[i] = v;
    }

    uint32_t smA = (uint32_t)__cvta_generic_to_shared(As);
    uint32_t smB = (uint32_t)__cvta_generic_to_shared(Bs);

    for (int k0 = 0; k0 < K; k0 += 32) {
#pragma unroll
        for (int i = 0; i < 2; i++) {
            int idx = i * 256 + tid;
            int row = idx >> 2, c8 = idx & 3;
            *(uint4*)(As + row * LDA + c8 * 8) = ra[i];
        }
#pragma unroll
        for (int i = 0; i < 2; i++) {
            int idx = i * 256 + tid;
            int kr = idx >> 4, nc4 = idx & 15;
            Bs[(nc4 * 4 + 0) * LDA + kr] = __float2bfloat16(rb[i].x);
            Bs[(nc4 * 4 + 1) * LDA + kr] = __float2bfloat16(rb[i].y);
            Bs[(nc4 * 4 + 2) * LDA + kr] = __float2bfloat16(rb[i].z);
            Bs[(nc4 * 4 + 3) * LDA + kr] = __float2bfloat16(rb[i].w);
        }
        __syncthreads();

        int kn = k0 + 32;
        if (kn < K) {
#pragma unroll
            for (int i = 0; i < 2; i++) {
                int idx = i * 256 + tid;
                int row = idx >> 2, c8 = idx & 3;
                int gr = bm + row;
                ra[i] = (gr < M) ? *(const uint4*)(A + (size_t)gr * K + kn + c8 * 8)
                                 : make_uint4(0u, 0u, 0u, 0u);
            }
#pragma unroll
            for (int i = 0; i < 2; i++) {
                int idx = i * 256 + tid;
                int kr = idx >> 4, nc4 = idx & 15;
                int gc = bn + nc4 * 4;
                const float* wp = W + (size_t)(kn + kr) * NCQ + gc;
                float4 v = make_float4(0.f, 0.f, 0.f, 0.f);
                if (NCQ >= 64 || gc + 3 < NCQ) {
                    if (NCQ >= 64 || gc < NCQ) v = *(const float4*)wp;
                } else {
                    if (gc + 0 < NCQ) v.x = wp[0];
                    if (gc + 1 < NCQ) v.y = wp[1];
                    if (gc + 2 < NCQ) v.z = wp[2];
                    if (gc + 3 < NCQ) v.w = wp[3];
                }
                rb[i] = v;
            }
        }

#pragma unroll
        for (int ks = 0; ks < 2; ks++) {
            int kk = ks * 16;
            uint32_t afr[2][4], bfr[4][2];
#pragma unroll
            for (int mt = 0; mt < 2; mt++) {
                int mrow = wm * 32 + mt * 16 + (lane & 15);
                int kc = kk + ((lane >> 4) << 3);
                ldsm4(afr[mt], smA + (uint32_t)(mrow * LDA + kc) * 2u);
            }
#pragma unroll
            for (int nh = 0; nh < 2; nh++) {
                int nrow = wn * 32 + nh * 16 + ((lane >> 4) << 3) + (lane & 7);
                int kc = kk + (((lane >> 3) & 1) << 3);
                uint32_t tmp[4];
                ldsm4(tmp, smB + (uint32_t)(nrow * LDA + kc) * 2u);
                bfr[nh * 2 + 0][0] = tmp[0]; bfr[nh * 2 + 0][1] = tmp[1];
                bfr[nh * 2 + 1][0] = tmp[2]; bfr[nh * 2 + 1][1] = tmp[3];
            }
#pragma unroll
            for (int mt = 0; mt < 2; mt++)
#pragma unroll
                for (int nt = 0; nt < 4; nt++)
                    mma_bf16(acc[mt][nt], afr[mt], bfr[nt]);
        }
        __syncthreads();
    }

    int gq = lane >> 2, tq = lane & 3;
    const float* asvh = asv + head * 64;
    const float* advh = adv + head * 64;
#pragma unroll
    for (int mt = 0; mt < 2; mt++) {
        float va0 = 0.f, va1 = 0.f, vd0 = 0.f, vd1 = 0.f;
        int r0 = bm + wm * 32 + mt * 16 + gq;
        int r1 = r0 + 8;
#pragma unroll
        for (int nt = 0; nt < 4; nt++) {
            int cl = wn * 32 + nt * 8 + tq * 2;
            float4 d = acc[mt][nt];
            if (r0 < M) store_c(C, (size_t)r0, NCQ, bn + cl, d.x, d.y, NCQ);
            if (r1 < M) store_c(C, (size_t)r1, NCQ, bn + cl, d.z, d.w, NCQ);
            float a0 = (NCQ >= 64 || cl + 0 < NCQ) ? asvh[cl] : 0.f;
            float a1 = (NCQ >= 64 || cl + 1 < NCQ) ? asvh[cl + 1] : 0.f;
            float e0 = (NCQ >= 64 || cl + 0 < NCQ) ? advh[cl] : 0.f;
            float e1 = (NCQ >= 64 || cl + 1 < NCQ) ? advh[cl + 1] : 0.f;
            va0 += d.x * a0 + d.y * a1;
            va1 += d.z * a0 + d.w * a1;
            vd0 += d.x * e0 + d.y * e1;
            vd1 += d.z * e0 + d.w * e1;
        }
#pragma unroll
        for (int o = 1; o <= 2; o <<= 1) {
            va0 += __shfl_xor_sync(0xffffffffu, va0, o);
            va1 += __shfl_xor_sync(0xffffffffu, va1, o);
            vd0 += __shfl_xor_sync(0xffffffffu, vd0, o);
            vd1 += __shfl_xor_sync(0xffffffffu, vd1, o);
        }
        if (tq == 0) {
            int lr = wm * 32 + mt * 16 + gq;
            sAls[lr][wn] = va0; sAls[lr + 8][wn] = va1;
            sAld[lr][wn] = vd0; sAld[lr + 8][wn] = vd1;
        }
    }
    __syncthreads();
    if (tid < 128) {
        int gr = bm + tid;
        if (gr < M) {
            als[(size_t)gr * HSTR + head] = sAls[tid][0] + sAls[tid][1];
            ald[(size_t)gr * HSTR + head] = sAld[tid][0] + sAld[tid][1];
        }
    }
}

// ====== fused attn+gather (layers 1-2): same loop bodies, one kernel ======
// Phase 1 == k_attnW4 body (den kept in registers). Phase 2 == k_gather256
// body (attn weights re-read are L1-hot; rden from register).
__global__ void k_ag256(const float4* __restrict__ als4, const float4* __restrict__ ald4,
                        float4* __restrict__ attn4,
                        const __nv_bfloat16* __restrict__ hb,
                        const float* __restrict__ bias,
                        __nv_bfloat16* __restrict__ out) {
    int w = (blockIdx.x * blockDim.x + threadIdx.x) >> 5;
    if (w >= NN) return;
    int lane = threadIdx.x & 31;
    int head = lane >> 3;
    int s0 = g_off[w], s1 = g_off[w + 1];

    // ---- phase 1: segment softmax (identical to k_attnW4) ----
    float4 ad = ald4[w];
    float4 m = make_float4(-1e30f, -1e30f, -1e30f, -1e30f);
    for (int i = s0 + lane; i < s1; i += 32) {
        int s = g_csr[i];
        float4 a = als4[s];
        a.x += ad.x; a.y += ad.y; a.z += ad.z; a.w += ad.w;
        a.x = (a.x > 0.f) ? a.x : NEG * a.x;
        a.y = (a.y > 0.f) ? a.y : NEG * a.y;
        a.z = (a.z > 0.f) ? a.z : NEG * a.z;
        a.w = (a.w > 0.f) ? a.w : NEG * a.w;
        attn4[i] = a;
        m.x = fmaxf(m.x, a.x); m.y = fmaxf(m.y, a.y);
        m.z = fmaxf(m.z, a.z); m.w = fmaxf(m.w, a.w);
    }
#pragma unroll
    for (int o = 16; o >= 1; o >>= 1) {
        m.x = fmaxf(m.x, __shfl_xor_sync(0xffffffffu, m.x, o));
        m.y = fmaxf(m.y, __shfl_xor_sync(0xffffffffu, m.y, o));
        m.z = fmaxf(m.z, __shfl_xor_sync(0xffffffffu, m.z, o));
        m.w = fmaxf(m.w, __shfl_xor_sync(0xffffffffu, m.w, o));
    }
    float4 den = make_float4(0.f, 0.f, 0.f, 0.f);
    for (int i = s0 + lane; i < s1; i += 32) {
        float4 a = attn4[i];
        a.x = __expf(a.x - m.x); a.y = __expf(a.y - m.y);
        a.z = __expf(a.z - m.z); a.w = __expf(a.w - m.w);
        attn4[i] = a;
        den.x += a.x; den.y += a.y; den.z += a.z; den.w += a.w;
    }
#pragma unroll
    for (int o = 16; o >= 1; o >>= 1) {
        den.x += __shfl_xor_sync(0xffffffffu, den.x, o);
        den.y += __shfl_xor_sync(0xffffffffu, den.y, o);
        den.z += __shfl_xor_sync(0xffffffffu, den.z, o);
        den.w += __shfl_xor_sync(0xffffffffu, den.w, o);
    }
    float rd = 1.f / ((head == 0) ? den.x : (head == 1) ? den.y : (head == 2) ? den.z : den.w);

    // ---- phase 2: gather (identical to k_gather256, rd from register) ----
    const float* attn = (const float*)attn4;
    float acc[8] = {0.f, 0.f, 0.f, 0.f, 0.f, 0.f, 0.f, 0.f};
    int i = s0;
    for (; i + 2 <= s1; i += 2) {
        int sA = g_csr[i];
        int sB = g_csr[i + 1];
        float wA = attn[(size_t)i * 4 + head];
        float wB = attn[(size_t)(i + 1) * 4 + head];
        uint4 uA = *(const uint4*)(hb + (size_t)sA * HC + lane * 8);
        uint4 uB = *(const uint4*)(hb + (size_t)sB * HC + lane * 8);
        float2 a0 = __bfloat1622float2(*(__nv_bfloat162*)&uA.x);
        float2 a1 = __bfloat1622float2(*(__nv_bfloat162*)&uA.y);
        float2 a2 = __bfloat1622float2(*(__nv_bfloat162*)&uA.z);
        float2 a3 = __bfloat1622float2(*(__nv_bfloat162*)&uA.w);
        acc[0] += wA * a0.x; acc[1] += wA * a0.y;
        acc[2] += wA * a1.x; acc[3] += wA * a1.y;
        acc[4] += wA * a2.x; acc[5] += wA * a2.y;
        acc[6] += wA * a3.x; acc[7] += wA * a3.y;
        float2 b0 = __bfloat1622float2(*(__nv_bfloat162*)&uB.x);
        float2 b1 = __bfloat1622float2(*(__nv_bfloat162*)&uB.y);
        float2 b2 = __bfloat1622float2(*(__nv_bfloat162*)&uB.z);
        float2 b3 = __bfloat1622float2(*(__nv_bfloat162*)&uB.w);
        acc[0] += wB * b0.x; acc[1] += wB * b0.y;
        acc[2] += wB * b1.x; acc[3] += wB * b1.y;
        acc[4] += wB * b2.x; acc[5] += wB * b2.y;
        acc[6] += wB * b3.x; acc[7] += wB * b3.y;
    }
    if (i < s1) {
        int s = g_csr[i];
        float wt = attn[(size_t)i * 4 + head];
        uint4 u = *(const uint4*)(hb + (size_t)s * HC + lane * 8);
        float2 f0 = __bfloat1622float2(*(__nv_bfloat162*)&u.x);
        float2 f1 = __bfloat1622float2(*(__nv_bfloat162*)&u.y);
        float2 f2 = __bfloat1622float2(*(__nv_bfloat162*)&u.z);
        float2 f3 = __bfloat1622float2(*(__nv_bfloat162*)&u.w);
        acc[0] += wt * f0.x; acc[1] += wt * f0.y;
        acc[2] += wt * f1.x; acc[3] += wt * f1.y;
        acc[4] += wt * f2.x; acc[5] += wt * f2.y;
        acc[6] += wt * f3.x; acc[7] += wt * f3.y;
    }
    float4 b0 = *(const float4*)(bias + lane * 8);
    float4 b1 = *(const float4*)(bias + lane * 8 + 4);
    float v[8];
    v[0] = fmaxf(acc[0] * rd + b0.x, 0.f); v[1] = fmaxf(acc[1] * rd + b0.y, 0.f);
    v[2] = fmaxf(acc[2] * rd + b0.z, 0.f); v[3] = fmaxf(acc[3] * rd + b0.w, 0.f);
    v[4] = fmaxf(acc[4] * rd + b1.x, 0.f); v[5] = fmaxf(acc[5] * rd + b1.y, 0.f);
    v[6] = fmaxf(acc[6] * rd + b1.z, 0.f); v[7] = fmaxf(acc[7] * rd + b1.w, 0.f);
    uint4 u;
    *(__nv_bfloat162*)&u.x = __float22bfloat162_rn(make_float2(v[0], v[1]));
    *(__nv_bfloat162*)&u.y = __float22bfloat162_rn(make_float2(v[2], v[3]));
    *(__nv_bfloat162*)&u.z = __float22bfloat162_rn(make_float2(v[4], v[5]));
    *(__nv_bfloat162*)&u.w = __float22bfloat162_rn(make_float2(v[6], v[7]));
    *(uint4*)(out + (size_t)w * HC + lane * 8) = u;
}

// ====== fused attn+gather+log_softmax (layer 3, H=1, fp32 h) ======
__global__ void k_ag40(const float* __restrict__ als, const float* __restrict__ ald,
                       float* __restrict__ attn,
                       const float* __restrict__ h,
                       const float* __restrict__ bias,
                       float* __restrict__ out) {
    int w = (blockIdx.x * blockDim.x + threadIdx.x) >> 5;
    if (w >= NN) return;
    int lane = threadIdx.x & 31;
    int s0 = g_off[w], s1 = g_off[w + 1];

    // ---- phase 1: segment softmax (identical to k_attnW1) ----
    float ad = ald[w];
    float m = -1e30f;
    for (int i = s0 + lane; i < s1; i += 32) {
        int s = g_csr[i];
        float a = als[s] + ad;
        a = (a > 0.f) ? a : NEG * a;
        attn[i] = a;
        m = fmaxf(m, a);
    }
#pragma unroll
    for (int o = 16; o >= 1; o >>= 1) m = fmaxf(m, __shfl_xor_sync(0xffffffffu, m, o));
    float den = 0.f;
    for (int i = s0 + lane; i < s1; i += 32) {
        float a = __expf(attn[i] - m);
        attn[i] = a;
        den += a;
    }
#pragma unroll
    for (int o = 16; o >= 1; o >>= 1) den += __shfl_xor_sync(0xffffffffu, den, o);
    float rd = 1.f / den;

    // ---- phase 2: gather + log_softmax (identical to k_gather40) ----
    float a0 = 0.f, a1 = 0.f;
    int i = s0;
    for (; i + 2 <= s1; i += 2) {
        int sA = g_csr[i];
        int sB = g_csr[i + 1];
        float wA = attn[i];
        float wB = attn[i + 1];
        const float* hA = h + (size_t)sA * OUTC;
        const float* hB = h + (size_t)sB * OUTC;
        float vA0 = hA[lane];
        float vB0 = hB[lane];
        float vA1 = (lane < 8) ? hA[32 + lane] : 0.f;
        float vB1 = (lane < 8) ? hB[32 + lane] : 0.f;
        a0 += wA * vA0 + wB * vB0;
        a1 += wA * vA1 + wB * vB1;
    }
    if (i < s1) {
        int s = g_csr[i];
        float wt = attn[i];
        const float* hr = h + (size_t)s * OUTC;
        a0 += wt * hr[lane];
        if (lane < 8) a1 += wt * hr[32 + lane];
    }
    float v0 = a0 * rd + bias[lane];
    float v1 = (lane < 8) ? (a1 * rd + bias[32 + lane]) : -1e30f;
    float mx = fmaxf(v0, v1);
#pragma unroll
    for (int o = 16; o >= 1; o >>= 1) mx = fmaxf(mx, __shfl_xor_sync(0xffffffffu, mx, o));
    float se = __expf(v0 - mx) + ((lane < 8) ? __expf(v1 - mx) : 0.f);
#pragma unroll
    for (int o = 16; o >= 1; o >>= 1) se += __shfl_xor_sync(0xffffffffu, se, o);
    float lse = mx + __logf(se);
    float* orow = out + (size_t)w * OUTC;
    orow[lane] = v0 - lse;
    if (lane < 8) orow[32 + lane] = v1 - lse;
}

// ---------------- launch ----------------
extern "C" void kernel_launch(void* const* d_in, const int* in_sizes, int n_in,
                              void* d_out, int out_size) {
    const float* x   = (const float*)d_in[0];
    const void*  ei  = d_in[1];
    const float* W1  = (const float*)d_in[2];
    const float* as1 = (const float*)d_in[3];
    const float* ad1 = (const float*)d_in[4];
    const float* b1  = (const float*)d_in[5];
    const float* W2  = (const float*)d_in[6];
    const float* as2 = (const float*)d_in[7];
    const float* ad2 = (const float*)d_in[8];
    const float* b2  = (const float*)d_in[9];
    const float* W3  = (const float*)d_in[10];
    const float* as3 = (const float*)d_in[11];
    const float* ad3 = (const float*)d_in[12];
    const float* b3  = (const float*)d_in[13];
    float* out = (float*)d_out;

    __nv_bfloat16 *xh, *bufHh, *bufAh;
    float *bufH3, *als, *ald, *attn;
    cudaGetSymbolAddress((void**)&xh,    g_xh);
    cudaGetSymbolAddress((void**)&bufHh, g_bufHh);
    cudaGetSymbolAddress((void**)&bufAh, g_bufAh);
    cudaGetSymbolAddress((void**)&bufH3, g_bufH3);
    cudaGetSymbolAddress((void**)&als,   g_als);
    cudaGetSymbolAddress((void**)&ald,   g_ald);
    cudaGetSymbolAddress((void**)&attn,  g_attn);

    const int TB = 256;
    int warpBlocks = (NN * 32 + TB - 1) / TB;
    int edgeBlocks = (ET + TB - 1) / TB;
    int scanBlocks = (NN + SB - 1) / SB;
    int prepBlocks = (NN * INC / 8 + TB - 1) / TB;

    // ---- prep + CSR build ----
    k_prep<<<prepBlocks, TB>>>(x, xh, (const int*)ei, NN * INC / 8);
    k_hist<<<edgeBlocks, TB>>>(ei);
    k_scan1<<<scanBlocks, SB>>>();
    k_scan3<<<scanBlocks, SB>>>(scanBlocks);
    k_scatter<<<edgeBlocks, TB>>>(ei);

    dim3 g1(4, (NN + 127) / 128);
    dim3 g3(1, (NN + 127) / 128);

    // ---- Layer 1 ----
    k_gemmb<HC, 4, __nv_bfloat16><<<g1, 256>>>(xh, W1, bufHh, as1, ad1, als, ald, NN, INC);
    k_ag256<<<warpBlocks, TB>>>((const float4*)als, (const float4*)ald,
                                (float4*)attn, bufHh, b1, bufAh);

    // ---- Layer 2 ----
    k_gemmb<HC, 4, __nv_bfloat16><<<g1, 256>>>(bufAh, W2, bufHh, as2, ad2, als, ald, NN, HC);
    k_ag256<<<warpBlocks, TB>>>((const float4*)als, (const float4*)ald,
                                (float4*)attn, bufHh, b2, bufAh);

    // ---- Layer 3 ----
    k_gemmb<OUTC, 1, float><<<g3, 256>>>(bufAh, W3, bufH3, as3, ad3, als, ald, NN, HC);
    k_ag40<<<warpBlocks, TB>>>(als, ald, attn, bufH3, b3, out);
}

// round 13
// speedup vs baseline: 1.1651x; 1.0224x over previous
#include <cuda_runtime.h>
#include <cuda_bf16.h>
#include <math.h>
#include <stdint.h>

#define NN   50000
#define EE   800000
#define ET   (EE + NN)    // edges + self loops = 850000
#define INC  128
#define HC   256          // HEADS*HID
#define OUTC 40
#define NEG  0.2f

// ---------------- device scratch (no allocations allowed) ----------------
__device__ __nv_bfloat16  g_xh[(size_t)NN * INC];    // bf16 copy of x
__device__ __nv_bfloat16  g_bufHh[(size_t)NN * HC];  // bf16 h (GEMM out, layers 1-2)
__device__ __nv_bfloat16  g_bufAh[(size_t)NN * HC];  // bf16 aggregated (next GEMM in)
__device__ float          g_bufH3[(size_t)NN * OUTC];// fp32 h (layer 3)
__device__ float g_als[(size_t)NN * 4];
__device__ float g_ald[(size_t)NN * 4];
__device__ float g_attn[(size_t)ET * 4];    // per-edge attention scratch
__device__ int   g_off[NN + 1];
__device__ int   g_cur[NN];
__device__ int   g_deg[NN];
__device__ int   g_csr[ET];
__device__ int   g_bsum[64];
__device__ int   g_i64flag;

__device__ __forceinline__ int edge_at(const void* ei, int f, long long pos) {
    return f ? (int)(((const long long*)ei)[pos]) : ((const int*)ei)[pos];
}

// ---------------- prep: dtype detect + zero counters + x->bf16 ------------
__global__ void k_prep(const float* __restrict__ x, __nv_bfloat16* __restrict__ xh,
                       const int* ei32, int n8) {
    int i = blockIdx.x * blockDim.x + threadIdx.x;
    if (i < n8) {
        const float4* p = (const float4*)(x + (size_t)i * 8);
        float4 a = p[0], b = p[1];
        uint4 u;
        *(__nv_bfloat162*)&u.x = __float22bfloat162_rn(make_float2(a.x, a.y));
        *(__nv_bfloat162*)&u.y = __float22bfloat162_rn(make_float2(a.z, a.w));
        *(__nv_bfloat162*)&u.z = __float22bfloat162_rn(make_float2(b.x, b.y));
        *(__nv_bfloat162*)&u.w = __float22bfloat162_rn(make_float2(b.z, b.w));
        *(uint4*)(xh + (size_t)i * 8) = u;
    }
    if (i < NN) { g_deg[i] = 0; g_cur[i] = 0; }
    if (blockIdx.x == 0) {
        int bad = 0;
        for (int j = threadIdx.x; j < 4096; j += blockDim.x)
            if (ei32[2 * j + 1] != 0) bad = 1;
        unsigned any = __ballot_sync(0xffffffffu, bad);
        __shared__ int sAny[8];
        if ((threadIdx.x & 31) == 0) sAny[threadIdx.x >> 5] = (any != 0);
        __syncthreads();
        if (threadIdx.x == 0) {
            int t = 0;
            for (int w = 0; w < (int)(blockDim.x >> 5); w++) t |= sAny[w];
            g_i64flag = t ? 0 : 1;
        }
    }
}

// ---------------- CSR build ----------------
__global__ void k_hist(const void* ei) {
    int e = blockIdx.x * blockDim.x + threadIdx.x;
    if (e >= ET) return;
    int f = g_i64flag;
    int d = (e < EE) ? edge_at(ei, f, (long long)EE + e) : (e - EE);
    atomicAdd(&g_deg[d], 1);
}

#define SB 1024
__global__ void k_scan1() {
    __shared__ int sh[SB];
    int g = blockIdx.x * SB + threadIdx.x;
    int v = (g < NN) ? g_deg[g] : 0;
    sh[threadIdx.x] = v;
    __syncthreads();
    for (int o = 1; o < SB; o <<= 1) {
        int t = (threadIdx.x >= o) ? sh[threadIdx.x - o] : 0;
        __syncthreads();
        sh[threadIdx.x] += t;
        __syncthreads();
    }
    if (g < NN) g_off[g] = sh[threadIdx.x] - v;   // exclusive
    if (threadIdx.x == SB - 1) g_bsum[blockIdx.x] = sh[SB - 1];
}
// scan3 computes the block-sum prefix itself
__global__ void k_scan3(int nb) {
    __shared__ int sC[2];
    int t = threadIdx.x;
    if (t < 64) {
        int v = (t < nb && t < (int)blockIdx.x) ? g_bsum[t] : 0;
#pragma unroll
        for (int o = 16; o >= 1; o >>= 1) v += __shfl_xor_sync(0xffffffffu, v, o);
        if ((t & 31) == 0) sC[t >> 5] = v;
    }
    __syncthreads();
    int carry = sC[0] + sC[1];
    int g = blockIdx.x * SB + t;
    if (g < NN) g_off[g] += carry;
    if (g == 0) g_off[NN] = ET;
}

__global__ void k_scatter(const void* ei) {
    int e = blockIdx.x * blockDim.x + threadIdx.x;
    if (e >= ET) return;
    int f = g_i64flag;
    int s, d;
    if (e < EE) { s = edge_at(ei, f, e); d = edge_at(ei, f, (long long)EE + e); }
    else        { s = d = e - EE; }
    int p = g_off[d] + atomicAdd(&g_cur[d], 1);
    g_csr[p] = s;
}

// ---------------- bf16 MMA helpers ----------------
__device__ __forceinline__ void ldsm4(uint32_t* r, uint32_t addr) {
    asm volatile("ldmatrix.sync.aligned.m8n8.x4.shared.b16 {%0,%1,%2,%3}, [%4];"
                 : "=r"(r[0]), "=r"(r[1]), "=r"(r[2]), "=r"(r[3]) : "r"(addr));
}

__device__ __forceinline__ void mma_bf16(float4& d, const uint32_t* a, const uint32_t* b) {
    asm volatile(
        "mma.sync.aligned.m16n8k16.row.col.f32.bf16.bf16.f32 "
        "{%0,%1,%2,%3}, {%4,%5,%6,%7}, {%8,%9}, {%0,%1,%2,%3};\n"
        : "+f"(d.x), "+f"(d.y), "+f"(d.z), "+f"(d.w)
        : "r"(a[0]), "r"(a[1]), "r"(a[2]), "r"(a[3]), "r"(b[0]), "r"(b[1]));
}

__device__ __forceinline__ void store_c(__nv_bfloat16* C, size_t r, int stride, int col,
                                        float x, float y, int ncq) {
    *(__nv_bfloat162*)(C + r * stride + col) = __float22bfloat162_rn(make_float2(x, y));
}
__device__ __forceinline__ void store_c(float* C, size_t r, int stride, int col,
                                        float x, float y, int ncq) {
    if (col < ncq) *(float2*)(C + r * stride + col) = make_float2(x, y);
}

#define LDA 40  // padded smem row stride in bf16 elems

// ============ bf16 GEMM + fused attention projections =====================
template<int NCQ, int HSTR, typename CT>
__global__ __launch_bounds__(256) void k_gemmb(const __nv_bfloat16* __restrict__ A,
                                               const float* __restrict__ W,
                                               CT* __restrict__ C,
                                               const float* __restrict__ asv,
                                               const float* __restrict__ adv,
                                               float* __restrict__ als,
                                               float* __restrict__ ald,
                                               int M, int K) {
    __shared__ __nv_bfloat16 As[128 * LDA];
    __shared__ __nv_bfloat16 Bs[64 * LDA];
    __shared__ float sAls[128][2];
    __shared__ float sAld[128][2];
    int tid = threadIdx.x;
    int lane = tid & 31, warp = tid >> 5;
    int wm = warp & 3, wn = warp >> 2;
    int bm = blockIdx.y * 128, bn = blockIdx.x * 64;
    int head = blockIdx.x;

    float4 acc[2][4];
#pragma unroll
    for (int mt = 0; mt < 2; mt++)
#pragma unroll
        for (int nt = 0; nt < 4; nt++) acc[mt][nt] = make_float4(0.f, 0.f, 0.f, 0.f);

    uint4  ra[2];
    float4 rb[2];

#pragma unroll
    for (int i = 0; i < 2; i++) {
        int idx = i * 256 + tid;
        int row = idx >> 2, c8 = idx & 3;
        int gr = bm + row;
        ra[i] = (gr < M) ? *(const uint4*)(A + (size_t)gr * K + c8 * 8)
                         : make_uint4(0u, 0u, 0u, 0u);
    }
#pragma unroll
    for (int i = 0; i < 2; i++) {
        int idx = i * 256 + tid;
        int kr = idx >> 4, nc4 = idx & 15;
        int gc = bn + nc4 * 4;
        const float* wp = W + (size_t)kr * NCQ + gc;
        float4 v = make_float4(0.f, 0.f, 0.f, 0.f);
        if (NCQ >= 64 || gc + 3 < NCQ) {
            if (NCQ >= 64 || gc < NCQ) v = *(const float4*)wp;
        } else {
            if (gc + 0 < NCQ) v.x = wp[0];
            if (gc + 1 < NCQ) v.y = wp[1];
            if (gc + 2 < NCQ) v.z = wp[2];
            if (gc + 3 < NCQ) v.w = wp[3];
        }
        rb[i] = v;
    }

    uint32_t smA = (uint32_t)__cvta_generic_to_shared(As);
    uint32_t smB = (uint32_t)__cvta_generic_to_shared(Bs);

    for (int k0 = 0; k0 < K; k0 += 32) {
#pragma unroll
        for (int i = 0; i < 2; i++) {
            int idx = i * 256 + tid;
            int row = idx >> 2, c8 = idx & 3;
            *(uint4*)(As + row * LDA + c8 * 8) = ra[i];
        }
#pragma unroll
        for (int i = 0; i < 2; i++) {
            int idx = i * 256 + tid;
            int kr = idx >> 4, nc4 = idx & 15;
            Bs[(nc4 * 4 + 0) * LDA + kr] = __float2bfloat16(rb[i].x);
            Bs[(nc4 * 4 + 1) * LDA + kr] = __float2bfloat16(rb[i].y);
            Bs[(nc4 * 4 + 2) * LDA + kr] = __float2bfloat16(rb[i].z);
            Bs[(nc4 * 4 + 3) * LDA + kr] = __float2bfloat16(rb[i].w);
        }
        __syncthreads();

        int kn = k0 + 32;
        if (kn < K) {
#pragma unroll
            for (int i = 0; i < 2; i++) {
                int idx = i * 256 + tid;
                int row = idx >> 2, c8 = idx & 3;
                int gr = bm + row;
                ra[i] = (gr < M) ? *(const uint4*)(A + (size_t)gr * K + kn + c8 * 8)
                                 : make_uint4(0u, 0u, 0u, 0u);
            }
#pragma unroll
            for (int i = 0; i < 2; i++) {
                int idx = i * 256 + tid;
                int kr = idx >> 4, nc4 = idx & 15;
                int gc = bn + nc4 * 4;
                const float* wp = W + (size_t)(kn + kr) * NCQ + gc;
                float4 v = make_float4(0.f, 0.f, 0.f, 0.f);
                if (NCQ >= 64 || gc + 3 < NCQ) {
                    if (NCQ >= 64 || gc < NCQ) v = *(const float4*)wp;
                } else {
                    if (gc + 0 < NCQ) v.x = wp[0];
                    if (gc + 1 < NCQ) v.y = wp[1];
                    if (gc + 2 < NCQ) v.z = wp[2];
                    if (gc + 3 < NCQ) v.w = wp[3];
                }
                rb[i] = v;
            }
        }

#pragma unroll
        for (int ks = 0; ks < 2; ks++) {
            int kk = ks * 16;
            uint32_t afr[2][4], bfr[4][2];
#pragma unroll
            for (int mt = 0; mt < 2; mt++) {
                int mrow = wm * 32 + mt * 16 + (lane & 15);
                int kc = kk + ((lane >> 4) << 3);
                ldsm4(afr[mt], smA + (uint32_t)(mrow * LDA + kc) * 2u);
            }
#pragma unroll
            for (int nh = 0; nh < 2; nh++) {
                int nrow = wn * 32 + nh * 16 + ((lane >> 4) << 3) + (lane & 7);
                int kc = kk + (((lane >> 3) & 1) << 3);
                uint32_t tmp[4];
                ldsm4(tmp, smB + (uint32_t)(nrow * LDA + kc) * 2u);
                bfr[nh * 2 + 0][0] = tmp[0]; bfr[nh * 2 + 0][1] = tmp[1];
                bfr[nh * 2 + 1][0] = tmp[2]; bfr[nh * 2 + 1][1] = tmp[3];
            }
#pragma unroll
            for (int mt = 0; mt < 2; mt++)
#pragma unroll
                for (int nt = 0; nt < 4; nt++)
                    mma_bf16(acc[mt][nt], afr[mt], bfr[nt]);
        }
        __syncthreads();
    }

    int gq = lane >> 2, tq = lane & 3;
    const float* asvh = asv + head * 64;
    const float* advh = adv + head * 64;
#pragma unroll
    for (int mt = 0; mt < 2; mt++) {
        float va0 = 0.f, va1 = 0.f, vd0 = 0.f, vd1 = 0.f;
        int r0 = bm + wm * 32 + mt * 16 + gq;
        int r1 = r0 + 8;
#pragma unroll
        for (int nt = 0; nt < 4; nt++) {
            int cl = wn * 32 + nt * 8 + tq * 2;
            float4 d = acc[mt][nt];
            if (r0 < M) store_c(C, (size_t)r0, NCQ, bn + cl, d.x, d.y, NCQ);
            if (r1 < M) store_c(C, (size_t)r1, NCQ, bn + cl, d.z, d.w, NCQ);
            float a0 = (NCQ >= 64 || cl + 0 < NCQ) ? asvh[cl] : 0.f;
            float a1 = (NCQ >= 64 || cl + 1 < NCQ) ? asvh[cl + 1] : 0.f;
            float e0 = (NCQ >= 64 || cl + 0 < NCQ) ? advh[cl] : 0.f;
            float e1 = (NCQ >= 64 || cl + 1 < NCQ) ? advh[cl + 1] : 0.f;
            va0 += d.x * a0 + d.y * a1;
            va1 += d.z * a0 + d.w * a1;
            vd0 += d.x * e0 + d.y * e1;
            vd1 += d.z * e0 + d.w * e1;
        }
#pragma unroll
        for (int o = 1; o <= 2; o <<= 1) {
            va0 += __shfl_xor_sync(0xffffffffu, va0, o);
            va1 += __shfl_xor_sync(0xffffffffu, va1, o);
            vd0 += __shfl_xor_sync(0xffffffffu, vd0, o);
            vd1 += __shfl_xor_sync(0xffffffffu, vd1, o);
        }
        if (tq == 0) {
            int lr = wm * 32 + mt * 16 + gq;
            sAls[lr][wn] = va0; sAls[lr + 8][wn] = va1;
            sAld[lr][wn] = vd0; sAld[lr + 8][wn] = vd1;
        }
    }
    __syncthreads();
    if (tid < 128) {
        int gr = bm + tid;
        if (gr < M) {
            als[(size_t)gr * HSTR + head] = sAls[tid][0] + sAls[tid][1];
            ald[(size_t)gr * HSTR + head] = sAld[tid][0] + sAld[tid][1];
        }
    }
}

// ====== fused attn+gather (layers 1-2): same loop bodies, one kernel ======
__global__ void k_ag256(const float4* __restrict__ als4, const float4* __restrict__ ald4,
                        float4* __restrict__ attn4,
                        const __nv_bfloat16* __restrict__ hb,
                        const float* __restrict__ bias,
                        __nv_bfloat16* __restrict__ out) {
    int w = (blockIdx.x * blockDim.x + threadIdx.x) >> 5;
    if (w >= NN) return;
    int lane = threadIdx.x & 31;
    int head = lane >> 3;
    int s0 = g_off[w], s1 = g_off[w + 1];

    // ---- phase 1: segment softmax ----
    float4 ad = ald4[w];
    float4 m = make_float4(-1e30f, -1e30f, -1e30f, -1e30f);
    for (int i = s0 + lane; i < s1; i += 32) {
        int s = g_csr[i];
        float4 a = als4[s];
        a.x += ad.x; a.y += ad.y; a.z += ad.z; a.w += ad.w;
        a.x = (a.x > 0.f) ? a.x : NEG * a.x;
        a.y = (a.y > 0.f) ? a.y : NEG * a.y;
        a.z = (a.z > 0.f) ? a.z : NEG * a.z;
        a.w = (a.w > 0.f) ? a.w : NEG * a.w;
        attn4[i] = a;
        m.x = fmaxf(m.x, a.x); m.y = fmaxf(m.y, a.y);
        m.z = fmaxf(m.z, a.z); m.w = fmaxf(m.w, a.w);
    }
#pragma unroll
    for (int o = 16; o >= 1; o >>= 1) {
        m.x = fmaxf(m.x, __shfl_xor_sync(0xffffffffu, m.x, o));
        m.y = fmaxf(m.y, __shfl_xor_sync(0xffffffffu, m.y, o));
        m.z = fmaxf(m.z, __shfl_xor_sync(0xffffffffu, m.z, o));
        m.w = fmaxf(m.w, __shfl_xor_sync(0xffffffffu, m.w, o));
    }
    float4 den = make_float4(0.f, 0.f, 0.f, 0.f);
    for (int i = s0 + lane; i < s1; i += 32) {
        float4 a = attn4[i];
        a.x = __expf(a.x - m.x); a.y = __expf(a.y - m.y);
        a.z = __expf(a.z - m.z); a.w = __expf(a.w - m.w);
        attn4[i] = a;
        den.x += a.x; den.y += a.y; den.z += a.z; den.w += a.w;
    }
#pragma unroll
    for (int o = 16; o >= 1; o >>= 1) {
        den.x += __shfl_xor_sync(0xffffffffu, den.x, o);
        den.y += __shfl_xor_sync(0xffffffffu, den.y, o);
        den.z += __shfl_xor_sync(0xffffffffu, den.z, o);
        den.w += __shfl_xor_sync(0xffffffffu, den.w, o);
    }
    float rd = 1.f / ((head == 0) ? den.x : (head == 1) ? den.y : (head == 2) ? den.z : den.w);

    // ---- phase 2: gather ----
    const float* attn = (const float*)attn4;
    float acc[8] = {0.f, 0.f, 0.f, 0.f, 0.f, 0.f, 0.f, 0.f};
    int i = s0;
    for (; i + 2 <= s1; i += 2) {
        int sA = g_csr[i];
        int sB = g_csr[i + 1];
        float wA = attn[(size_t)i * 4 + head];
        float wB = attn[(size_t)(i + 1) * 4 + head];
        uint4 uA = *(const uint4*)(hb + (size_t)sA * HC + lane * 8);
        uint4 uB = *(const uint4*)(hb + (size_t)sB * HC + lane * 8);
        float2 a0 = __bfloat1622float2(*(__nv_bfloat162*)&uA.x);
        float2 a1 = __bfloat1622float2(*(__nv_bfloat162*)&uA.y);
        float2 a2 = __bfloat1622float2(*(__nv_bfloat162*)&uA.z);
        float2 a3 = __bfloat1622float2(*(__nv_bfloat162*)&uA.w);
        acc[0] += wA * a0.x; acc[1] += wA * a0.y;
        acc[2] += wA * a1.x; acc[3] += wA * a1.y;
        acc[4] += wA * a2.x; acc[5] += wA * a2.y;
        acc[6] += wA * a3.x; acc[7] += wA * a3.y;
        float2 b0 = __bfloat1622float2(*(__nv_bfloat162*)&uB.x);
        float2 b1 = __bfloat1622float2(*(__nv_bfloat162*)&uB.y);
        float2 b2 = __bfloat1622float2(*(__nv_bfloat162*)&uB.z);
        float2 b3 = __bfloat1622float2(*(__nv_bfloat162*)&uB.w);
        acc[0] += wB * b0.x; acc[1] += wB * b0.y;
        acc[2] += wB * b1.x; acc[3] += wB * b1.y;
        acc[4] += wB * b2.x; acc[5] += wB * b2.y;
        acc[6] += wB * b3.x; acc[7] += wB * b3.y;
    }
    if (i < s1) {
        int s = g_csr[i];
        float wt = attn[(size_t)i * 4 + head];
        uint4 u = *(const uint4*)(hb + (size_t)s * HC + lane * 8);
        float2 f0 = __bfloat1622float2(*(__nv_bfloat162*)&u.x);
        float2 f1 = __bfloat1622float2(*(__nv_bfloat162*)&u.y);
        float2 f2 = __bfloat1622float2(*(__nv_bfloat162*)&u.z);
        float2 f3 = __bfloat1622float2(*(__nv_bfloat162*)&u.w);
        acc[0] += wt * f0.x; acc[1] += wt * f0.y;
        acc[2] += wt * f1.x; acc[3] += wt * f1.y;
        acc[4] += wt * f2.x; acc[5] += wt * f2.y;
        acc[6] += wt * f3.x; acc[7] += wt * f3.y;
    }
    float4 b0 = *(const float4*)(bias + lane * 8);
    float4 b1 = *(const float4*)(bias + lane * 8 + 4);
    float v[8];
    v[0] = fmaxf(acc[0] * rd + b0.x, 0.f); v[1] = fmaxf(acc[1] * rd + b0.y, 0.f);
    v[2] = fmaxf(acc[2] * rd + b0.z, 0.f); v[3] = fmaxf(acc[3] * rd + b0.w, 0.f);
    v[4] = fmaxf(acc[4] * rd + b1.x, 0.f); v[5] = fmaxf(acc[5] * rd + b1.y, 0.f);
    v[6] = fmaxf(acc[6] * rd + b1.z, 0.f); v[7] = fmaxf(acc[7] * rd + b1.w, 0.f);
    uint4 u;
    *(__nv_bfloat162*)&u.x = __float22bfloat162_rn(make_float2(v[0], v[1]));
    *(__nv_bfloat162*)&u.y = __float22bfloat162_rn(make_float2(v[2], v[3]));
    *(__nv_bfloat162*)&u.z = __float22bfloat162_rn(make_float2(v[4], v[5]));
    *(__nv_bfloat162*)&u.w = __float22bfloat162_rn(make_float2(v[6], v[7]));
    *(uint4*)(out + (size_t)w * HC + lane * 8) = u;
}

// ====== fused attn+gather+log_softmax (layer 3, H=1, fp32 h) ======
__global__ void k_ag40(const float* __restrict__ als, const float* __restrict__ ald,
                       float* __restrict__ attn,
                       const float* __restrict__ h,
                       const float* __restrict__ bias,
                       float* __restrict__ out) {
    int w = (blockIdx.x * blockDim.x + threadIdx.x) >> 5;
    if (w >= NN) return;
    int lane = threadIdx.x & 31;
    int s0 = g_off[w], s1 = g_off[w + 1];

    // ---- phase 1: segment softmax ----
    float ad = ald[w];
    float m = -1e30f;
    for (int i = s0 + lane; i < s1; i += 32) {
        int s = g_csr[i];
        float a = als[s] + ad;
        a = (a > 0.f) ? a : NEG * a;
        attn[i] = a;
        m = fmaxf(m, a);
    }
#pragma unroll
    for (int o = 16; o >= 1; o >>= 1) m = fmaxf(m, __shfl_xor_sync(0xffffffffu, m, o));
    float den = 0.f;
    for (int i = s0 + lane; i < s1; i += 32) {
        float a = __expf(attn[i] - m);
        attn[i] = a;
        den += a;
    }
#pragma unroll
    for (int o = 16; o >= 1; o >>= 1) den += __shfl_xor_sync(0xffffffffu, den, o);
    float rd = 1.f / den;

    // ---- phase 2: gather + log_softmax ----
    float a0 = 0.f, a1 = 0.f;
    int i = s0;
    for (; i + 2 <= s1; i += 2) {
        int sA = g_csr[i];
        int sB = g_csr[i + 1];
        float wA = attn[i];
        float wB = attn[i + 1];
        const float* hA = h + (size_t)sA * OUTC;
        const float* hB = h + (size_t)sB * OUTC;
        float vA0 = hA[lane];
        float vB0 = hB[lane];
        float vA1 = (lane < 8) ? hA[32 + lane] : 0.f;
        float vB1 = (lane < 8) ? hB[32 + lane] : 0.f;
        a0 += wA * vA0 + wB * vB0;
        a1 += wA * vA1 + wB * vB1;
    }
    if (i < s1) {
        int s = g_csr[i];
        float wt = attn[i];
        const float* hr = h + (size_t)s * OUTC;
        a0 += wt * hr[lane];
        if (lane < 8) a1 += wt * hr[32 + lane];
    }
    float v0 = a0 * rd + bias[lane];
    float v1 = (lane < 8) ? (a1 * rd + bias[32 + lane]) : -1e30f;
    float mx = fmaxf(v0, v1);
#pragma unroll
    for (int o = 16; o >= 1; o >>= 1) mx = fmaxf(mx, __shfl_xor_sync(0xffffffffu, mx, o));
    float se = __expf(v0 - mx) + ((lane < 8) ? __expf(v1 - mx) : 0.f);
#pragma unroll
    for (int o = 16; o >= 1; o >>= 1) se += __shfl_xor_sync(0xffffffffu, se, o);
    float lse = mx + __logf(se);
    float* orow = out + (size_t)w * OUTC;
    orow[lane] = v0 - lse;
    if (lane < 8) orow[32 + lane] = v1 - lse;
}

// ---------------- launch ----------------
extern "C" void kernel_launch(void* const* d_in, const int* in_sizes, int n_in,
                              void* d_out, int out_size) {
    const float* x   = (const float*)d_in[0];
    const void*  ei  = d_in[1];
    const float* W1  = (const float*)d_in[2];
    const float* as1 = (const float*)d_in[3];
    const float* ad1 = (const float*)d_in[4];
    const float* b1  = (const float*)d_in[5];
    const float* W2  = (const float*)d_in[6];
    const float* as2 = (const float*)d_in[7];
    const float* ad2 = (const float*)d_in[8];
    const float* b2  = (const float*)d_in[9];
    const float* W3  = (const float*)d_in[10];
    const float* as3 = (const float*)d_in[11];
    const float* ad3 = (const float*)d_in[12];
    const float* b3  = (const float*)d_in[13];
    float* out = (float*)d_out;

    __nv_bfloat16 *xh, *bufHh, *bufAh;
    float *bufH3, *als, *ald, *attn;
    cudaGetSymbolAddress((void**)&xh,    g_xh);
    cudaGetSymbolAddress((void**)&bufHh, g_bufHh);
    cudaGetSymbolAddress((void**)&bufAh, g_bufAh);
    cudaGetSymbolAddress((void**)&bufH3, g_bufH3);
    cudaGetSymbolAddress((void**)&als,   g_als);
    cudaGetSymbolAddress((void**)&ald,   g_ald);
    cudaGetSymbolAddress((void**)&attn,  g_attn);

    const int TB = 256;
    int warpBlocks = (NN * 32 + TB - 1) / TB;
    int edgeBlocks = (ET + TB - 1) / TB;
    int scanBlocks = (NN + SB - 1) / SB;
    int prepBlocks = (NN * INC / 8 + TB - 1) / TB;

    // Side stream + events for CSR/GEMM1 overlap (baked into the captured
    // graph as node dependencies; created per call, intentionally not
    // destroyed — destroying a forked stream mid-capture can invalidate it,
    // and host-side cost is irrelevant after capture).
    cudaStream_t sCsr;
    cudaStreamCreateWithFlags(&sCsr, cudaStreamNonBlocking);
    cudaEvent_t evFork, evJoin;
    cudaEventCreateWithFlags(&evFork, cudaEventDisableTiming);
    cudaEventCreateWithFlags(&evJoin, cudaEventDisableTiming);

    // ---- prep (produces xh + zeroed counters + dtype flag) ----
    k_prep<<<prepBlocks, TB>>>(x, xh, (const int*)ei, NN * INC / 8);

    // fork: CSR chain runs concurrently with layer-1 GEMM
    cudaEventRecord(evFork, 0);
    cudaStreamWaitEvent(sCsr, evFork, 0);
    k_hist<<<edgeBlocks, TB, 0, sCsr>>>(ei);
    k_scan1<<<scanBlocks, SB, 0, sCsr>>>();
    k_scan3<<<scanBlocks, SB, 0, sCsr>>>(scanBlocks);
    k_scatter<<<edgeBlocks, TB, 0, sCsr>>>(ei);
    cudaEventRecord(evJoin, sCsr);

    dim3 g1(4, (NN + 127) / 128);
    dim3 g3(1, (NN + 127) / 128);

    // ---- Layer 1 GEMM (independent of CSR) ----
    k_gemmb<HC, 4, __nv_bfloat16><<<g1, 256>>>(xh, W1, bufHh, as1, ad1, als, ald, NN, INC);

    // join: gather needs the CSR
    cudaStreamWaitEvent(0, evJoin, 0);
    k_ag256<<<warpBlocks, TB>>>((const float4*)als, (const float4*)ald,
                                (float4*)attn, bufHh, b1, bufAh);

    // ---- Layer 2 ----
    k_gemmb<HC, 4, __nv_bfloat16><<<g1, 256>>>(bufAh, W2, bufHh, as2, ad2, als, ald, NN, HC);
    k_ag256<<<warpBlocks, TB>>>((const float4*)als, (const float4*)ald,
                                (float4*)attn, bufHh, b2, bufAh);

    // ---- Layer 3 ----
    k_gemmb<OUTC, 1, float><<<g3, 256>>>(bufAh, W3, bufH3, as3, ad3, als, ald, NN, HC);
    k_ag40<<<warpBlocks, TB>>>(als, ald, attn, bufH3, b3, out);
}

// round 14
// speedup vs baseline: 1.1748x; 1.0084x over previous
#include <cuda_runtime.h>
#include <cuda_bf16.h>
#include <math.h>
#include <stdint.h>

#define NN   50000
#define EE   800000
#define ET   (EE + NN)    // edges + self loops = 850000
#define INC  128
#define HC   256          // HEADS*HID
#define OUTC 40
#define NEG  0.2f

// ---------------- device scratch (no allocations allowed) ----------------
__device__ __nv_bfloat16  g_xh[(size_t)NN * INC];    // bf16 copy of x
__device__ __nv_bfloat16  g_bufHh[(size_t)NN * HC];  // bf16 h (GEMM out, layers 1-2)
__device__ __nv_bfloat16  g_bufAh[(size_t)NN * HC];  // bf16 aggregated (next GEMM in)
__device__ float          g_bufH3[(size_t)NN * OUTC];// fp32 h (layer 3)
__device__ float g_als[(size_t)NN * 4];
__device__ float g_ald[(size_t)NN * 4];
__device__ float g_attn[(size_t)ET * 4];    // per-edge attention scratch
__device__ int   g_off[NN + 1];
__device__ int   g_cur[NN];
__device__ int   g_deg[NN];
__device__ int   g_csr[ET];
__device__ int   g_bsum[64];
__device__ int   g_i64flag;

__device__ __forceinline__ int edge_at(const void* ei, int f, long long pos) {
    return f ? (int)(((const long long*)ei)[pos]) : ((const int*)ei)[pos];
}

// ---------------- zero counters + dtype detect (tiny, runs first) ---------
__global__ void k_zerodetect(const int* ei32) {
    int i = blockIdx.x * blockDim.x + threadIdx.x;
    if (i < NN) { g_deg[i] = 0; g_cur[i] = 0; }
    if (blockIdx.x == 0) {
        int bad = 0;
        for (int j = threadIdx.x; j < 4096; j += blockDim.x)
            if (ei32[2 * j + 1] != 0) bad = 1;
        unsigned any = __ballot_sync(0xffffffffu, bad);
        __shared__ int sAny[8];
        if ((threadIdx.x & 31) == 0) sAny[threadIdx.x >> 5] = (any != 0);
        __syncthreads();
        if (threadIdx.x == 0) {
            int t = 0;
            for (int w = 0; w < (int)(blockDim.x >> 5); w++) t |= sAny[w];
            g_i64flag = t ? 0 : 1;
        }
    }
}

// ---------------- x -> bf16 ----------------
__global__ void k_cvt(const float* __restrict__ x, __nv_bfloat16* __restrict__ xh, int n8) {
    int i = blockIdx.x * blockDim.x + threadIdx.x;
    if (i >= n8) return;
    const float4* p = (const float4*)(x + (size_t)i * 8);
    float4 a = p[0], b = p[1];
    uint4 u;
    *(__nv_bfloat162*)&u.x = __float22bfloat162_rn(make_float2(a.x, a.y));
    *(__nv_bfloat162*)&u.y = __float22bfloat162_rn(make_float2(a.z, a.w));
    *(__nv_bfloat162*)&u.z = __float22bfloat162_rn(make_float2(b.x, b.y));
    *(__nv_bfloat162*)&u.w = __float22bfloat162_rn(make_float2(b.z, b.w));
    *(uint4*)(xh + (size_t)i * 8) = u;
}

// ---------------- CSR build ----------------
__global__ void k_hist(const void* ei) {
    int e = blockIdx.x * blockDim.x + threadIdx.x;
    if (e >= ET) return;
    int f = g_i64flag;
    int d = (e < EE) ? edge_at(ei, f, (long long)EE + e) : (e - EE);
    atomicAdd(&g_deg[d], 1);
}

#define SB 1024
__global__ void k_scan1() {
    __shared__ int sh[SB];
    int g = blockIdx.x * SB + threadIdx.x;
    int v = (g < NN) ? g_deg[g] : 0;
    sh[threadIdx.x] = v;
    __syncthreads();
    for (int o = 1; o < SB; o <<= 1) {
        int t = (threadIdx.x >= o) ? sh[threadIdx.x - o] : 0;
        __syncthreads();
        sh[threadIdx.x] += t;
        __syncthreads();
    }
    if (g < NN) g_off[g] = sh[threadIdx.x] - v;   // exclusive
    if (threadIdx.x == SB - 1) g_bsum[blockIdx.x] = sh[SB - 1];
}
// scan3 computes the block-sum prefix itself
__global__ void k_scan3(int nb) {
    __shared__ int sC[2];
    int t = threadIdx.x;
    if (t < 64) {
        int v = (t < nb && t < (int)blockIdx.x) ? g_bsum[t] : 0;
#pragma unroll
        for (int o = 16; o >= 1; o >>= 1) v += __shfl_xor_sync(0xffffffffu, v, o);
        if ((t & 31) == 0) sC[t >> 5] = v;
    }
    __syncthreads();
    int carry = sC[0] + sC[1];
    int g = blockIdx.x * SB + t;
    if (g < NN) g_off[g] += carry;
    if (g == 0) g_off[NN] = ET;
}

__global__ void k_scatter(const void* ei) {
    int e = blockIdx.x * blockDim.x + threadIdx.x;
    if (e >= ET) return;
    int f = g_i64flag;
    int s, d;
    if (e < EE) { s = edge_at(ei, f, e); d = edge_at(ei, f, (long long)EE + e); }
    else        { s = d = e - EE; }
    int p = g_off[d] + atomicAdd(&g_cur[d], 1);
    g_csr[p] = s;
}

// ---------------- bf16 MMA helpers ----------------
__device__ __forceinline__ void ldsm4(uint32_t* r, uint32_t addr) {
    asm volatile("ldmatrix.sync.aligned.m8n8.x4.shared.b16 {%0,%1,%2,%3}, [%4];"
                 : "=r"(r[0]), "=r"(r[1]), "=r"(r[2]), "=r"(r[3]) : "r"(addr));
}

__device__ __forceinline__ void mma_bf16(float4& d, const uint32_t* a, const uint32_t* b) {
    asm volatile(
        "mma.sync.aligned.m16n8k16.row.col.f32.bf16.bf16.f32 "
        "{%0,%1,%2,%3}, {%4,%5,%6,%7}, {%8,%9}, {%0,%1,%2,%3};\n"
        : "+f"(d.x), "+f"(d.y), "+f"(d.z), "+f"(d.w)
        : "r"(a[0]), "r"(a[1]), "r"(a[2]), "r"(a[3]), "r"(b[0]), "r"(b[1]));
}

__device__ __forceinline__ void store_c(__nv_bfloat16* C, size_t r, int stride, int col,
                                        float x, float y, int ncq) {
    *(__nv_bfloat162*)(C + r * stride + col) = __float22bfloat162_rn(make_float2(x, y));
}
__device__ __forceinline__ void store_c(float* C, size_t r, int stride, int col,
                                        float x, float y, int ncq) {
    if (col < ncq) *(float2*)(C + r * stride + col) = make_float2(x, y);
}

#define LDA 40  // padded smem row stride in bf16 elems

// ============ bf16 GEMM (double-buffered smem) + fused attn projections ===
template<int NCQ, int HSTR, typename CT>
__global__ __launch_bounds__(256) void k_gemmb(const __nv_bfloat16* __restrict__ A,
                                               const float* __restrict__ W,
                                               CT* __restrict__ C,
                                               const float* __restrict__ asv,
                                               const float* __restrict__ adv,
                                               float* __restrict__ als,
                                               float* __restrict__ ald,
                                               int M, int K) {
    __shared__ __nv_bfloat16 As[2][128 * LDA];
    __shared__ __nv_bfloat16 Bs[2][64 * LDA];
    __shared__ float sAls[128][2];
    __shared__ float sAld[128][2];
    int tid = threadIdx.x;
    int lane = tid & 31, warp = tid >> 5;
    int wm = warp & 3, wn = warp >> 2;
    int bm = blockIdx.y * 128, bn = blockIdx.x * 64;
    int head = blockIdx.x;

    float4 acc[2][4];
#pragma unroll
    for (int mt = 0; mt < 2; mt++)
#pragma unroll
        for (int nt = 0; nt < 4; nt++) acc[mt][nt] = make_float4(0.f, 0.f, 0.f, 0.f);

    uint4  ra[2];
    float4 rb[2];

    // thread's fixed staging coordinates
    int arow0 = (tid) >> 2,        ac8_0 = (tid) & 3;
    int arow1 = (256 + tid) >> 2,  ac8_1 = (256 + tid) & 3;
    int wkr0 = (tid) >> 4,         wnc0 = (tid) & 15;
    int wkr1 = (256 + tid) >> 4,   wnc1 = (256 + tid) & 15;

    // ---- prologue: load tile 0 into regs, store to buffer 0 ----
    {
        int gr0 = bm + arow0, gr1 = bm + arow1;
        ra[0] = (gr0 < M) ? *(const uint4*)(A + (size_t)gr0 * K + ac8_0 * 8)
                          : make_uint4(0u, 0u, 0u, 0u);
        ra[1] = (gr1 < M) ? *(const uint4*)(A + (size_t)gr1 * K + ac8_1 * 8)
                          : make_uint4(0u, 0u, 0u, 0u);
#pragma unroll
        for (int i = 0; i < 2; i++) {
            int kr = i ? wkr1 : wkr0, nc4 = i ? wnc1 : wnc0;
            int gc = bn + nc4 * 4;
            const float* wp = W + (size_t)kr * NCQ + gc;
            float4 v = make_float4(0.f, 0.f, 0.f, 0.f);
            if (NCQ >= 64 || gc + 3 < NCQ) {
                if (NCQ >= 64 || gc < NCQ) v = *(const float4*)wp;
            } else {
                if (gc + 0 < NCQ) v.x = wp[0];
                if (gc + 1 < NCQ) v.y = wp[1];
                if (gc + 2 < NCQ) v.z = wp[2];
                if (gc + 3 < NCQ) v.w = wp[3];
            }
            rb[i] = v;
        }
        *(uint4*)(As[0] + arow0 * LDA + ac8_0 * 8) = ra[0];
        *(uint4*)(As[0] + arow1 * LDA + ac8_1 * 8) = ra[1];
#pragma unroll
        for (int i = 0; i < 2; i++) {
            int kr = i ? wkr1 : wkr0, nc4 = i ? wnc1 : wnc0;
            Bs[0][(nc4 * 4 + 0) * LDA + kr] = __float2bfloat16(rb[i].x);
            Bs[0][(nc4 * 4 + 1) * LDA + kr] = __float2bfloat16(rb[i].y);
            Bs[0][(nc4 * 4 + 2) * LDA + kr] = __float2bfloat16(rb[i].z);
            Bs[0][(nc4 * 4 + 3) * LDA + kr] = __float2bfloat16(rb[i].w);
        }
    }
    __syncthreads();

    int p = 0;
    for (int k0 = 0; k0 < K; k0 += 32, p ^= 1) {
        int kn = k0 + 32;
        // issue global loads for next tile early (overlap with mma)
        if (kn < K) {
            int gr0 = bm + arow0, gr1 = bm + arow1;
            ra[0] = (gr0 < M) ? *(const uint4*)(A + (size_t)gr0 * K + kn + ac8_0 * 8)
                              : make_uint4(0u, 0u, 0u, 0u);
            ra[1] = (gr1 < M) ? *(const uint4*)(A + (size_t)gr1 * K + kn + ac8_1 * 8)
                              : make_uint4(0u, 0u, 0u, 0u);
#pragma unroll
            for (int i = 0; i < 2; i++) {
                int kr = i ? wkr1 : wkr0, nc4 = i ? wnc1 : wnc0;
                int gc = bn + nc4 * 4;
                const float* wp = W + (size_t)(kn + kr) * NCQ + gc;
                float4 v = make_float4(0.f, 0.f, 0.f, 0.f);
                if (NCQ >= 64 || gc + 3 < NCQ) {
                    if (NCQ >= 64 || gc < NCQ) v = *(const float4*)wp;
                } else {
                    if (gc + 0 < NCQ) v.x = wp[0];
                    if (gc + 1 < NCQ) v.y = wp[1];
                    if (gc + 2 < NCQ) v.z = wp[2];
                    if (gc + 3 < NCQ) v.w = wp[3];
                }
                rb[i] = v;
            }
        }

        uint32_t smA = (uint32_t)__cvta_generic_to_shared(As[p]);
        uint32_t smB = (uint32_t)__cvta_generic_to_shared(Bs[p]);
#pragma unroll
        for (int ks = 0; ks < 2; ks++) {
            int kk = ks * 16;
            uint32_t afr[2][4], bfr[4][2];
#pragma unroll
            for (int mt = 0; mt < 2; mt++) {
                int mrow = wm * 32 + mt * 16 + (lane & 15);
                int kc = kk + ((lane >> 4) << 3);
                ldsm4(afr[mt], smA + (uint32_t)(mrow * LDA + kc) * 2u);
            }
#pragma unroll
            for (int nh = 0; nh < 2; nh++) {
                int nrow = wn * 32 + nh * 16 + ((lane >> 4) << 3) + (lane & 7);
                int kc = kk + (((lane >> 3) & 1) << 3);
                uint32_t tmp[4];
                ldsm4(tmp, smB + (uint32_t)(nrow * LDA + kc) * 2u);
                bfr[nh * 2 + 0][0] = tmp[0]; bfr[nh * 2 + 0][1] = tmp[1];
                bfr[nh * 2 + 1][0] = tmp[2]; bfr[nh * 2 + 1][1] = tmp[3];
            }
#pragma unroll
            for (int mt = 0; mt < 2; mt++)
#pragma unroll
                for (int nt = 0; nt < 4; nt++)
                    mma_bf16(acc[mt][nt], afr[mt], bfr[nt]);
        }

        // store next tile into the other buffer (safe: sync at end of
        // previous iteration guarantees its readers are done)
        if (kn < K) {
            int q = p ^ 1;
            *(uint4*)(As[q] + arow0 * LDA + ac8_0 * 8) = ra[0];
            *(uint4*)(As[q] + arow1 * LDA + ac8_1 * 8) = ra[1];
#pragma unroll
            for (int i = 0; i < 2; i++) {
                int kr = i ? wkr1 : wkr0, nc4 = i ? wnc1 : wnc0;
                Bs[q][(nc4 * 4 + 0) * LDA + kr] = __float2bfloat16(rb[i].x);
                Bs[q][(nc4 * 4 + 1) * LDA + kr] = __float2bfloat16(rb[i].y);
                Bs[q][(nc4 * 4 + 2) * LDA + kr] = __float2bfloat16(rb[i].z);
                Bs[q][(nc4 * 4 + 3) * LDA + kr] = __float2bfloat16(rb[i].w);
            }
        }
        __syncthreads();
    }

    int gq = lane >> 2, tq = lane & 3;
    const float* asvh = asv + head * 64;
    const float* advh = adv + head * 64;
#pragma unroll
    for (int mt = 0; mt < 2; mt++) {
        float va0 = 0.f, va1 = 0.f, vd0 = 0.f, vd1 = 0.f;
        int r0 = bm + wm * 32 + mt * 16 + gq;
        int r1 = r0 + 8;
#pragma unroll
        for (int nt = 0; nt < 4; nt++) {
            int cl = wn * 32 + nt * 8 + tq * 2;
            float4 d = acc[mt][nt];
            if (r0 < M) store_c(C, (size_t)r0, NCQ, bn + cl, d.x, d.y, NCQ);
            if (r1 < M) store_c(C, (size_t)r1, NCQ, bn + cl, d.z, d.w, NCQ);
            float a0 = (NCQ >= 64 || cl + 0 < NCQ) ? asvh[cl] : 0.f;
            float a1 = (NCQ >= 64 || cl + 1 < NCQ) ? asvh[cl + 1] : 0.f;
            float e0 = (NCQ >= 64 || cl + 0 < NCQ) ? advh[cl] : 0.f;
            float e1 = (NCQ >= 64 || cl + 1 < NCQ) ? advh[cl + 1] : 0.f;
            va0 += d.x * a0 + d.y * a1;
            va1 += d.z * a0 + d.w * a1;
            vd0 += d.x * e0 + d.y * e1;
            vd1 += d.z * e0 + d.w * e1;
        }
#pragma unroll
        for (int o = 1; o <= 2; o <<= 1) {
            va0 += __shfl_xor_sync(0xffffffffu, va0, o);
            va1 += __shfl_xor_sync(0xffffffffu, va1, o);
            vd0 += __shfl_xor_sync(0xffffffffu, vd0, o);
            vd1 += __shfl_xor_sync(0xffffffffu, vd1, o);
        }
        if (tq == 0) {
            int lr = wm * 32 + mt * 16 + gq;
            sAls[lr][wn] = va0; sAls[lr + 8][wn] = va1;
            sAld[lr][wn] = vd0; sAld[lr + 8][wn] = vd1;
        }
    }
    __syncthreads();
    if (tid < 128) {
        int gr = bm + tid;
        if (gr < M) {
            als[(size_t)gr * HSTR + head] = sAls[tid][0] + sAls[tid][1];
            ald[(size_t)gr * HSTR + head] = sAld[tid][0] + sAld[tid][1];
        }
    }
}

// ====== fused attn+gather (layers 1-2): same loop bodies, one kernel ======
__global__ void k_ag256(const float4* __restrict__ als4, const float4* __restrict__ ald4,
                        float4* __restrict__ attn4,
                        const __nv_bfloat16* __restrict__ hb,
                        const float* __restrict__ bias,
                        __nv_bfloat16* __restrict__ out) {
    int w = (blockIdx.x * blockDim.x + threadIdx.x) >> 5;
    if (w >= NN) return;
    int lane = threadIdx.x & 31;
    int head = lane >> 3;
    int s0 = g_off[w], s1 = g_off[w + 1];

    // ---- phase 1: segment softmax ----
    float4 ad = ald4[w];
    float4 m = make_float4(-1e30f, -1e30f, -1e30f, -1e30f);
    for (int i = s0 + lane; i < s1; i += 32) {
        int s = g_csr[i];
        float4 a = als4[s];
        a.x += ad.x; a.y += ad.y; a.z += ad.z; a.w += ad.w;
        a.x = (a.x > 0.f) ? a.x : NEG * a.x;
        a.y = (a.y > 0.f) ? a.y : NEG * a.y;
        a.z = (a.z > 0.f) ? a.z : NEG * a.z;
        a.w = (a.w > 0.f) ? a.w : NEG * a.w;
        attn4[i] = a;
        m.x = fmaxf(m.x, a.x); m.y = fmaxf(m.y, a.y);
        m.z = fmaxf(m.z, a.z); m.w = fmaxf(m.w, a.w);
    }
#pragma unroll
    for (int o = 16; o >= 1; o >>= 1) {
        m.x = fmaxf(m.x, __shfl_xor_sync(0xffffffffu, m.x, o));
        m.y = fmaxf(m.y, __shfl_xor_sync(0xffffffffu, m.y, o));
        m.z = fmaxf(m.z, __shfl_xor_sync(0xffffffffu, m.z, o));
        m.w = fmaxf(m.w, __shfl_xor_sync(0xffffffffu, m.w, o));
    }
    float4 den = make_float4(0.f, 0.f, 0.f, 0.f);
    for (int i = s0 + lane; i < s1; i += 32) {
        float4 a = attn4[i];
        a.x = __expf(a.x - m.x); a.y = __expf(a.y - m.y);
        a.z = __expf(a.z - m.z); a.w = __expf(a.w - m.w);
        attn4[i] = a;
        den.x += a.x; den.y += a.y; den.z += a.z; den.w += a.w;
    }
#pragma unroll
    for (int o = 16; o >= 1; o >>= 1) {
        den.x += __shfl_xor_sync(0xffffffffu, den.x, o);
        den.y += __shfl_xor_sync(0xffffffffu, den.y, o);
        den.z += __shfl_xor_sync(0xffffffffu, den.z, o);
        den.w += __shfl_xor_sync(0xffffffffu, den.w, o);
    }
    float rd = 1.f / ((head == 0) ? den.x : (head == 1) ? den.y : (head == 2) ? den.z : den.w);

    // ---- phase 2: gather ----
    const float* attn = (const float*)attn4;
    float acc[8] = {0.f, 0.f, 0.f, 0.f, 0.f, 0.f, 0.f, 0.f};
    int i = s0;
    for (; i + 2 <= s1; i += 2) {
        int sA = g_csr[i];
        int sB = g_csr[i + 1];
        float wA = attn[(size_t)i * 4 + head];
        float wB = attn[(size_t)(i + 1) * 4 + head];
        uint4 uA = *(const uint4*)(hb + (size_t)sA * HC + lane * 8);
        uint4 uB = *(const uint4*)(hb + (size_t)sB * HC + lane * 8);
        float2 a0 = __bfloat1622float2(*(__nv_bfloat162*)&uA.x);
        float2 a1 = __bfloat1622float2(*(__nv_bfloat162*)&uA.y);
        float2 a2 = __bfloat1622float2(*(__nv_bfloat162*)&uA.z);
        float2 a3 = __bfloat1622float2(*(__nv_bfloat162*)&uA.w);
        acc[0] += wA * a0.x; acc[1] += wA * a0.y;
        acc[2] += wA * a1.x; acc[3] += wA * a1.y;
        acc[4] += wA * a2.x; acc[5] += wA * a2.y;
        acc[6] += wA * a3.x; acc[7] += wA * a3.y;
        float2 b0 = __bfloat1622float2(*(__nv_bfloat162*)&uB.x);
        float2 b1 = __bfloat1622float2(*(__nv_bfloat162*)&uB.y);
        float2 b2 = __bfloat1622float2(*(__nv_bfloat162*)&uB.z);
        float2 b3 = __bfloat1622float2(*(__nv_bfloat162*)&uB.w);
        acc[0] += wB * b0.x; acc[1] += wB * b0.y;
        acc[2] += wB * b1.x; acc[3] += wB * b1.y;
        acc[4] += wB * b2.x; acc[5] += wB * b2.y;
        acc[6] += wB * b3.x; acc[7] += wB * b3.y;
    }
    if (i < s1) {
        int s = g_csr[i];
        float wt = attn[(size_t)i * 4 + head];
        uint4 u = *(const uint4*)(hb + (size_t)s * HC + lane * 8);
        float2 f0 = __bfloat1622float2(*(__nv_bfloat162*)&u.x);
        float2 f1 = __bfloat1622float2(*(__nv_bfloat162*)&u.y);
        float2 f2 = __bfloat1622float2(*(__nv_bfloat162*)&u.z);
        float2 f3 = __bfloat1622float2(*(__nv_bfloat162*)&u.w);
        acc[0] += wt * f0.x; acc[1] += wt * f0.y;
        acc[2] += wt * f1.x; acc[3] += wt * f1.y;
        acc[4] += wt * f2.x; acc[5] += wt * f2.y;
        acc[6] += wt * f3.x; acc[7] += wt * f3.y;
    }
    float4 b0 = *(const float4*)(bias + lane * 8);
    float4 b1 = *(const float4*)(bias + lane * 8 + 4);
    float v[8];
    v[0] = fmaxf(acc[0] * rd + b0.x, 0.f); v[1] = fmaxf(acc[1] * rd + b0.y, 0.f);
    v[2] = fmaxf(acc[2] * rd + b0.z, 0.f); v[3] = fmaxf(acc[3] * rd + b0.w, 0.f);
    v[4] = fmaxf(acc[4] * rd + b1.x, 0.f); v[5] = fmaxf(acc[5] * rd + b1.y, 0.f);
    v[6] = fmaxf(acc[6] * rd + b1.z, 0.f); v[7] = fmaxf(acc[7] * rd + b1.w, 0.f);
    uint4 u;
    *(__nv_bfloat162*)&u.x = __float22bfloat162_rn(make_float2(v[0], v[1]));
    *(__nv_bfloat162*)&u.y = __float22bfloat162_rn(make_float2(v[2], v[3]));
    *(__nv_bfloat162*)&u.z = __float22bfloat162_rn(make_float2(v[4], v[5]));
    *(__nv_bfloat162*)&u.w = __float22bfloat162_rn(make_float2(v[6], v[7]));
    *(uint4*)(out + (size_t)w * HC + lane * 8) = u;
}

// ====== fused attn+gather+log_softmax (layer 3, H=1, fp32 h) ======
__global__ void k_ag40(const float* __restrict__ als, const float* __restrict__ ald,
                       float* __restrict__ attn,
                       const float* __restrict__ h,
                       const float* __restrict__ bias,
                       float* __restrict__ out) {
    int w = (blockIdx.x * blockDim.x + threadIdx.x) >> 5;
    if (w >= NN) return;
    int lane = threadIdx.x & 31;
    int s0 = g_off[w], s1 = g_off[w + 1];

    // ---- phase 1: segment softmax ----
    float ad = ald[w];
    float m = -1e30f;
    for (int i = s0 + lane; i < s1; i += 32) {
        int s = g_csr[i];
        float a = als[s] + ad;
        a = (a > 0.f) ? a : NEG * a;
        attn[i] = a;
        m = fmaxf(m, a);
    }
#pragma unroll
    for (int o = 16; o >= 1; o >>= 1) m = fmaxf(m, __shfl_xor_sync(0xffffffffu, m, o));
    float den = 0.f;
    for (int i = s0 + lane; i < s1; i += 32) {
        float a = __expf(attn[i] - m);
        attn[i] = a;
        den += a;
    }
#pragma unroll
    for (int o = 16; o >= 1; o >>= 1) den += __shfl_xor_sync(0xffffffffu, den, o);
    float rd = 1.f / den;

    // ---- phase 2: gather + log_softmax ----
    float a0 = 0.f, a1 = 0.f;
    int i = s0;
    for (; i + 2 <= s1; i += 2) {
        int sA = g_csr[i];
        int sB = g_csr[i + 1];
        float wA = attn[i];
        float wB = attn[i + 1];
        const float* hA = h + (size_t)sA * OUTC;
        const float* hB = h + (size_t)sB * OUTC;
        float vA0 = hA[lane];
        float vB0 = hB[lane];
        float vA1 = (lane < 8) ? hA[32 + lane] : 0.f;
        float vB1 = (lane < 8) ? hB[32 + lane] : 0.f;
        a0 += wA * vA0 + wB * vB0;
        a1 += wA * vA1 + wB * vB1;
    }
    if (i < s1) {
        int s = g_csr[i];
        float wt = attn[i];
        const float* hr = h + (size_t)s * OUTC;
        a0 += wt * hr[lane];
        if (lane < 8) a1 += wt * hr[32 + lane];
    }
    float v0 = a0 * rd + bias[lane];
    float v1 = (lane < 8) ? (a1 * rd + bias[32 + lane]) : -1e30f;
    float mx = fmaxf(v0, v1);
#pragma unroll
    for (int o = 16; o >= 1; o >>= 1) mx = fmaxf(mx, __shfl_xor_sync(0xffffffffu, mx, o));
    float se = __expf(v0 - mx) + ((lane < 8) ? __expf(v1 - mx) : 0.f);
#pragma unroll
    for (int o = 16; o >= 1; o >>= 1) se += __shfl_xor_sync(0xffffffffu, se, o);
    float lse = mx + __logf(se);
    float* orow = out + (size_t)w * OUTC;
    orow[lane] = v0 - lse;
    if (lane < 8) orow[32 + lane] = v1 - lse;
}

// ---------------- launch ----------------
extern "C" void kernel_launch(void* const* d_in, const int* in_sizes, int n_in,
                              void* d_out, int out_size) {
    const float* x   = (const float*)d_in[0];
    const void*  ei  = d_in[1];
    const float* W1  = (const float*)d_in[2];
    const float* as1 = (const float*)d_in[3];
    const float* ad1 = (const float*)d_in[4];
    const float* b1  = (const float*)d_in[5];
    const float* W2  = (const float*)d_in[6];
    const float* as2 = (const float*)d_in[7];
    const float* ad2 = (const float*)d_in[8];
    const float* b2  = (const float*)d_in[9];
    const float* W3  = (const float*)d_in[10];
    const float* as3 = (const float*)d_in[11];
    const float* ad3 = (const float*)d_in[12];
    const float* b3  = (const float*)d_in[13];
    float* out = (float*)d_out;

    __nv_bfloat16 *xh, *bufHh, *bufAh;
    float *bufH3, *als, *ald, *attn;
    cudaGetSymbolAddress((void**)&xh,    g_xh);
    cudaGetSymbolAddress((void**)&bufHh, g_bufHh);
    cudaGetSymbolAddress((void**)&bufAh, g_bufAh);
    cudaGetSymbolAddress((void**)&bufH3, g_bufH3);
    cudaGetSymbolAddress((void**)&als,   g_als);
    cudaGetSymbolAddress((void**)&ald,   g_ald);
    cudaGetSymbolAddress((void**)&attn,  g_attn);

    const int TB = 256;
    int warpBlocks = (NN * 32 + TB - 1) / TB;
    int edgeBlocks = (ET + TB - 1) / TB;
    int scanBlocks = (NN + SB - 1) / SB;
    int cvtBlocks  = (NN * INC / 8 + TB - 1) / TB;
    int zdBlocks   = (NN + TB - 1) / TB;

    // Side stream + events for CSR/(cvt+GEMM1) overlap (baked into the
    // captured graph as node dependencies; created per call, intentionally
    // not destroyed — see R10 rationale).
    cudaStream_t sCsr;
    cudaStreamCreateWithFlags(&sCsr, cudaStreamNonBlocking);
    cudaEvent_t evFork, evJoin;
    cudaEventCreateWithFlags(&evFork, cudaEventDisableTiming);
    cudaEventCreateWithFlags(&evJoin, cudaEventDisableTiming);

    // ---- tiny prep (counters + dtype flag only) ----
    k_zerodetect<<<zdBlocks, TB>>>((const int*)ei);

    // fork immediately: CSR chain runs concurrently with x-cvt AND layer-1 GEMM
    cudaEventRecord(evFork, 0);
    cudaStreamWaitEvent(sCsr, evFork, 0);
    k_hist<<<edgeBlocks, TB, 0, sCsr>>>(ei);
    k_scan1<<<scanBlocks, SB, 0, sCsr>>>();
    k_scan3<<<scanBlocks, SB, 0, sCsr>>>(scanBlocks);
    k_scatter<<<edgeBlocks, TB, 0, sCsr>>>(ei);
    cudaEventRecord(evJoin, sCsr);

    dim3 g1(4, (NN + 127) / 128);
    dim3 g3(1, (NN + 127) / 128);

    // ---- main stream: x conversion + layer-1 GEMM (independent of CSR) ----
    k_cvt<<<cvtBlocks, TB>>>(x, xh, NN * INC / 8);
    k_gemmb<HC, 4, __nv_bfloat16><<<g1, 256>>>(xh, W1, bufHh, as1, ad1, als, ald, NN, INC);

    // join: gather needs the CSR
    cudaStreamWaitEvent(0, evJoin, 0);
    k_ag256<<<warpBlocks, TB>>>((const float4*)als, (const float4*)ald,
                                (float4*)attn, bufHh, b1, bufAh);

    // ---- Layer 2 ----
    k_gemmb<HC, 4, __nv_bfloat16><<<g1, 256>>>(bufAh, W2, bufHh, as2, ad2, als, ald, NN, HC);
    k_ag256<<<warpBlocks, TB>>>((const float4*)als, (const float4*)ald,
                                (float4*)attn, bufHh, b2, bufAh);

    // ---- Layer 3 ----
    k_gemmb<OUTC, 1, float><<<g3, 256>>>(bufAh, W3, bufH3, as3, ad3, als, ald, NN, HC);
    k_ag40<<<warpBlocks, TB>>>(als, ald, attn, bufH3, b3, out);
}